// round 1
// baseline (speedup 1.0000x reference)
#include <cuda_runtime.h>
#include <math.h>

// ---------------------------------------------------------------------------
// Problem constants (B=1)
//   S=2048, H=2048, COMP=1024, T=S+COMP=3072, KV_DIM=512, FF=5632
//   NH=32, NKV=8, HD=64, GROUPS=4, DEPTH=2, EPS=1e-6
// All GEMM dims are multiples of 128 -> no edge handling anywhere.
// ---------------------------------------------------------------------------

// Device-global scratch (allocation-free; ~117 MB)
__device__ float g_residual[3072 * 2048];
__device__ float g_compressed[1024 * 2048];
__device__ float g_ct[1024 * 2048];
__device__ float g_q[1024 * 2048];
__device__ float g_k[3072 * 512];
__device__ float g_v[3072 * 512];
__device__ float g_attno[1024 * 2048];
__device__ float g_gate[1024 * 5632];
__device__ float g_up[1024 * 5632];

// ---------------------------------------------------------------------------
// Tiled SGEMM: C[M,N] = A[M,K] @ (TRANSB ? B[N,K]^T : B[K,N])  (+ epilogue)
// EPI: 0 = none, 1 = + aux[row] (row bias), 2 = + aux[row*N+col] (residual)
// BM=BN=128, BK=16, 256 threads, 8x8 per thread.
// ---------------------------------------------------------------------------
template <bool TRANSB, int EPI>
__global__ __launch_bounds__(256, 2) void gemm_kernel(
    const float* __restrict__ A, const float* __restrict__ B,
    float* __restrict__ C, const float* __restrict__ aux,
    int M, int N, int K)
{
    __shared__ float As[16][132];   // As[k][m]
    __shared__ float Bs[16][132];   // Bs[k][n]

    const int tid = threadIdx.x;
    const int tr = tid >> 4;        // 0..15
    const int tc = tid & 15;        // 0..15
    const int m0 = blockIdx.y * 128;
    const int n0 = blockIdx.x * 128;

    float acc[8][8];
#pragma unroll
    for (int i = 0; i < 8; i++)
#pragma unroll
        for (int j = 0; j < 8; j++) acc[i][j] = 0.f;

    for (int k0 = 0; k0 < K; k0 += 16) {
        // A tile: 128 rows x 16 k, float4 along k, stored transposed
#pragma unroll
        for (int i = 0; i < 2; i++) {
            int flat = tid + i * 256;          // 512 float4 slots
            int r = flat >> 2;                 // 0..127
            int kq = (flat & 3) << 2;          // 0,4,8,12
            float4 va = *(const float4*)(A + (size_t)(m0 + r) * K + k0 + kq);
            As[kq + 0][r] = va.x; As[kq + 1][r] = va.y;
            As[kq + 2][r] = va.z; As[kq + 3][r] = va.w;
        }
        if (TRANSB) {
#pragma unroll
            for (int i = 0; i < 2; i++) {
                int flat = tid + i * 256;
                int r = flat >> 2;             // 0..127 (n index)
                int kq = (flat & 3) << 2;
                float4 vb = *(const float4*)(B + (size_t)(n0 + r) * K + k0 + kq);
                Bs[kq + 0][r] = vb.x; Bs[kq + 1][r] = vb.y;
                Bs[kq + 2][r] = vb.z; Bs[kq + 3][r] = vb.w;
            }
        } else {
#pragma unroll
            for (int i = 0; i < 2; i++) {
                int flat = tid + i * 256;      // 512 float4 slots: 16 k-rows x 32
                int r = flat >> 5;             // 0..15 (k index)
                int cq = (flat & 31) << 2;     // 0..124
                float4 vb = *(const float4*)(B + (size_t)(k0 + r) * N + n0 + cq);
                *(float4*)&Bs[r][cq] = vb;     // 132 floats = 528B: 16B-aligned rows
            }
        }
        __syncthreads();

#pragma unroll
        for (int kk = 0; kk < 16; kk++) {
            float a[8], b[8];
#pragma unroll
            for (int i = 0; i < 8; i++) a[i] = As[kk][tr * 8 + i];
#pragma unroll
            for (int j = 0; j < 8; j++) b[j] = Bs[kk][tc * 8 + j];
#pragma unroll
            for (int i = 0; i < 8; i++)
#pragma unroll
                for (int j = 0; j < 8; j++) acc[i][j] += a[i] * b[j];
        }
        __syncthreads();
    }

#pragma unroll
    for (int i = 0; i < 8; i++) {
        int row = m0 + tr * 8 + i;
#pragma unroll
        for (int j = 0; j < 8; j++) {
            int col = n0 + tc * 8 + j;
            float v = acc[i][j];
            if (EPI == 1) v += aux[row];
            if (EPI == 2) v += aux[(size_t)row * N + col];
            C[(size_t)row * N + col] = v;
        }
    }
}

// ---------------------------------------------------------------------------
// RMSNorm over H=2048: y = x * rsqrt(mean(x^2) + eps) * w
// one block per row
// ---------------------------------------------------------------------------
__global__ void rmsnorm_kernel(const float* __restrict__ x,
                               const float* __restrict__ w,
                               float* __restrict__ y)
{
    const int row = blockIdx.x;
    const float* xr = x + (size_t)row * 2048;
    float ss = 0.f;
    for (int i = threadIdx.x; i < 2048; i += 256) { float v = xr[i]; ss += v * v; }
    __shared__ float red[256];
    red[threadIdx.x] = ss;
    __syncthreads();
    for (int s = 128; s > 0; s >>= 1) {
        if (threadIdx.x < s) red[threadIdx.x] += red[threadIdx.x + s];
        __syncthreads();
    }
    __shared__ float inv;
    if (threadIdx.x == 0) inv = rsqrtf(red[0] * (1.f / 2048.f) + 1e-6f);
    __syncthreads();
    float iv = inv;
    for (int i = threadIdx.x; i < 2048; i += 256)
        y[(size_t)row * 2048 + i] = xr[i] * iv * w[i];
}

// ---------------------------------------------------------------------------
// GQA flash attention, fp32, full softmax over T=3072.
// grid = (COMP/64 q-tiles, 32 heads), 256 threads.
// BQ=64, BT=32. Q ld = 2048 (cols head*64..), K/V ld = 512 (cols (head/4)*64..)
// ---------------------------------------------------------------------------
__global__ __launch_bounds__(256) void attn_kernel(
    const float* __restrict__ Q, const float* __restrict__ K,
    const float* __restrict__ V, float* __restrict__ O)
{
    __shared__ float Qs[64][68];
    __shared__ float Ks[32][68];
    __shared__ float Vs[32][68];
    __shared__ float Ss[64][36];
    __shared__ float mrow[64], lrow[64], frow[64];

    const int tid = threadIdx.x;
    const int q0 = blockIdx.x * 64;
    const int head = blockIdx.y;
    const int kvoff = (head >> 2) * 64;

    // Load Q tile (64 x 64)
#pragma unroll
    for (int i = 0; i < 4; i++) {
        int flat = tid + i * 256;         // 1024 float4 slots
        int r = flat >> 4;                // 0..63
        int c = (flat & 15) << 2;         // 0..60
        float4 v = *(const float4*)(Q + (size_t)(q0 + r) * 2048 + head * 64 + c);
        *(float4*)&Qs[r][c] = v;
    }
    if (tid < 64) { mrow[tid] = -1e30f; lrow[tid] = 0.f; }

    const int qr0 = (tid >> 4) * 4;       // 4 q rows per thread
    const int kc0 = (tid & 15) * 2;       // 2 score cols per thread
    const int dc0 = (tid & 15) * 4;       // 4 output dims per thread

    float acc[4][4];
#pragma unroll
    for (int i = 0; i < 4; i++)
#pragma unroll
        for (int j = 0; j < 4; j++) acc[i][j] = 0.f;

    for (int t0 = 0; t0 < 3072; t0 += 32) {
        __syncthreads();   // previous PV done before K/V/S smem reuse
#pragma unroll
        for (int i = 0; i < 2; i++) {
            int flat = tid + i * 256;     // 512 float4 slots (32 rows x 16)
            int r = flat >> 4;            // 0..31
            int c = (flat & 15) << 2;
            *(float4*)&Ks[r][c] = *(const float4*)(K + (size_t)(t0 + r) * 512 + kvoff + c);
            *(float4*)&Vs[r][c] = *(const float4*)(V + (size_t)(t0 + r) * 512 + kvoff + c);
        }
        __syncthreads();

        // S = Q @ K^T * 1/8 ; each thread: 4x2 of the 64x32 tile
        float s[4][2];
#pragma unroll
        for (int i = 0; i < 4; i++) { s[i][0] = 0.f; s[i][1] = 0.f; }
#pragma unroll
        for (int d = 0; d < 64; d++) {
            float qv[4], kv[2];
#pragma unroll
            for (int i = 0; i < 4; i++) qv[i] = Qs[qr0 + i][d];
            kv[0] = Ks[kc0 + 0][d];
            kv[1] = Ks[kc0 + 1][d];
#pragma unroll
            for (int i = 0; i < 4; i++) {
                s[i][0] += qv[i] * kv[0];
                s[i][1] += qv[i] * kv[1];
            }
        }
#pragma unroll
        for (int i = 0; i < 4; i++) {
            Ss[qr0 + i][kc0 + 0] = s[i][0] * 0.125f;
            Ss[qr0 + i][kc0 + 1] = s[i][1] * 0.125f;
        }
        __syncthreads();

        // Online softmax row stats (one thread per q row)
        if (tid < 64) {
            int r = tid;
            float mt = mrow[r];
            for (int c = 0; c < 32; c++) mt = fmaxf(mt, Ss[r][c]);
            float f = __expf(mrow[r] - mt);
            float l = lrow[r] * f;
            for (int c = 0; c < 32; c++) {
                float p = __expf(Ss[r][c] - mt);
                Ss[r][c] = p;
                l += p;
            }
            mrow[r] = mt; lrow[r] = l; frow[r] = f;
        }
        __syncthreads();

        // Rescale accumulators, then O += P @ V
#pragma unroll
        for (int i = 0; i < 4; i++) {
            float f = frow[qr0 + i];
#pragma unroll
            for (int j = 0; j < 4; j++) acc[i][j] *= f;
        }
#pragma unroll
        for (int kc = 0; kc < 32; kc++) {
            float p[4], v[4];
#pragma unroll
            for (int i = 0; i < 4; i++) p[i] = Ss[qr0 + i][kc];
#pragma unroll
            for (int j = 0; j < 4; j++) v[j] = Vs[kc][dc0 + j];
#pragma unroll
            for (int i = 0; i < 4; i++)
#pragma unroll
                for (int j = 0; j < 4; j++) acc[i][j] += p[i] * v[j];
        }
    }

#pragma unroll
    for (int i = 0; i < 4; i++) {
        float il = 1.f / lrow[qr0 + i];
#pragma unroll
        for (int j = 0; j < 4; j++)
            O[(size_t)(q0 + qr0 + i) * 2048 + head * 64 + dc0 + j] = acc[i][j] * il;
    }
}

// ---------------------------------------------------------------------------
// SwiGLU: g = silu(g) * u
// ---------------------------------------------------------------------------
__global__ void swiglu_kernel(float* __restrict__ g, const float* __restrict__ u, int n)
{
    int i = blockIdx.x * blockDim.x + threadIdx.x;
    if (i < n) {
        float x = g[i];
        float s = x / (1.f + __expf(-x));
        g[i] = s * u[i];
    }
}

// float4 copy
__global__ void copy_kernel(float* __restrict__ dst, const float* __restrict__ src, int n4)
{
    int i = blockIdx.x * blockDim.x + threadIdx.x;
    if (i < n4) ((float4*)dst)[i] = ((const float4*)src)[i];
}

// ---------------------------------------------------------------------------
// Orchestration
// ---------------------------------------------------------------------------
extern "C" void kernel_launch(void* const* d_in, const int* in_sizes, int n_in,
                              void* d_out, int out_size)
{
    const float* hidden      = (const float*)d_in[0];
    const float* comp_w      = (const float*)d_in[1];
    const float* comp_b      = (const float*)d_in[2];
    const float* q_w         = (const float*)d_in[3];
    const float* k_w         = (const float*)d_in[4];
    const float* v_w         = (const float*)d_in[5];
    const float* o_w         = (const float*)d_in[6];
    const float* attn_norm_w = (const float*)d_in[7];
    const float* mlp_norm_w  = (const float*)d_in[8];
    const float* gate_w      = (const float*)d_in[9];
    const float* up_w        = (const float*)d_in[10];
    const float* down_w      = (const float*)d_in[11];
    float* out = (float*)d_out;

    float *residual, *compressed, *ct, *q, *k, *v, *attno, *gate, *up;
    cudaGetSymbolAddress((void**)&residual,   g_residual);
    cudaGetSymbolAddress((void**)&compressed, g_compressed);
    cudaGetSymbolAddress((void**)&ct,         g_ct);
    cudaGetSymbolAddress((void**)&q,          g_q);
    cudaGetSymbolAddress((void**)&k,          g_k);
    cudaGetSymbolAddress((void**)&v,          g_v);
    cudaGetSymbolAddress((void**)&attno,      g_attno);
    cudaGetSymbolAddress((void**)&gate,       g_gate);
    cudaGetSymbolAddress((void**)&up,         g_up);

    // compressed = comp_w[1024,2048] @ hidden[2048,2048] + comp_b  (B not transposed)
    gemm_kernel<false, 1><<<dim3(16, 8), 256>>>(comp_w, hidden, compressed, comp_b,
                                                1024, 2048, 2048);
    // residual rows [0:2048) = hidden
    copy_kernel<<<(2048 * 2048 / 4 + 255) / 256, 256>>>(residual, hidden, 2048 * 2048 / 4);

    for (int layer = 0; layer < 2; layer++) {
        // residual rows [2048:3072) = compressed
        copy_kernel<<<(1024 * 2048 / 4 + 255) / 256, 256>>>(
            residual + 2048 * 2048, compressed, 1024 * 2048 / 4);

        // ct = rmsnorm(compressed, attn_norm_w)
        rmsnorm_kernel<<<1024, 256>>>(compressed, attn_norm_w, ct);

        // q = ct @ q_w^T ; k,v = residual @ {k,v}_w^T
        gemm_kernel<true, 0><<<dim3(16, 8), 256>>>(ct, q_w, q, nullptr, 1024, 2048, 2048);
        gemm_kernel<true, 0><<<dim3(4, 24), 256>>>(residual, k_w, k, nullptr, 3072, 512, 2048);
        gemm_kernel<true, 0><<<dim3(4, 24), 256>>>(residual, v_w, v, nullptr, 3072, 512, 2048);

        // attention (GQA, softmax over full T=3072)
        attn_kernel<<<dim3(16, 32), 256>>>(q, k, v, attno);

        // compressed = attno @ o_w^T + ct
        gemm_kernel<true, 2><<<dim3(16, 8), 256>>>(attno, o_w, compressed, ct, 1024, 2048, 2048);

        // ct2 = rmsnorm(compressed, mlp_norm_w)
        rmsnorm_kernel<<<1024, 256>>>(compressed, mlp_norm_w, ct);

        // gate/up projections
        gemm_kernel<true, 0><<<dim3(44, 8), 256>>>(ct, gate_w, gate, nullptr, 1024, 5632, 2048);
        gemm_kernel<true, 0><<<dim3(44, 8), 256>>>(ct, up_w, up, nullptr, 1024, 5632, 2048);

        // gate = silu(gate) * up
        swiglu_kernel<<<(1024 * 5632 + 255) / 256, 256>>>(gate, up, 1024 * 5632);

        // compressed = gate @ down_w^T + ct2   (last layer writes d_out directly)
        float* dst = (layer == 1) ? out : compressed;
        gemm_kernel<true, 2><<<dim3(16, 8), 256>>>(gate, down_w, dst, ct, 1024, 2048, 5632);
    }
}

// round 4
// speedup vs baseline: 2.0516x; 2.0516x over previous
#include <cuda_runtime.h>
#include <cuda_bf16.h>
#include <cstdint>
#include <math.h>

// ===========================================================================
// Problem: S=2048, H=2048, COMP=1024, T=3072, KV_DIM=512, FF=5632,
//          NH=32, NKV=8, HD=64, DEPTH=2.
// tcgen05 unavailable at compute_103 (no 'a'). GEMMs: mma.sync.m16n8k16 bf16
// with hi/lo 3-product split. cp.async 3-stage pipeline. fp32 SIMT attention.
// ===========================================================================

// -------------------- device-global scratch (no allocs) --------------------
__device__ float g_compressed[1024 * 2048];
__device__ float g_ct[1024 * 2048];
__device__ float g_q[1024 * 2048];
__device__ float g_k[3072 * 512];
__device__ float g_v[3072 * 512];
__device__ float g_attno[1024 * 2048];
__device__ float g_gate[1024 * 5632];
__device__ float g_up[1024 * 5632];

__device__ __nv_bfloat16 g_res_hi[3072 * 2048], g_res_lo[3072 * 2048];
__device__ __nv_bfloat16 g_ct_hi[1024 * 2048], g_ct_lo[1024 * 2048];
__device__ __nv_bfloat16 g_ao_hi[1024 * 2048], g_ao_lo[1024 * 2048];
__device__ __nv_bfloat16 g_ga_hi[1024 * 5632], g_ga_lo[1024 * 5632];
__device__ __nv_bfloat16 g_hT_hi[2048 * 2048], g_hT_lo[2048 * 2048];

__device__ __nv_bfloat16 g_cw_hi[1024 * 2048], g_cw_lo[1024 * 2048];
__device__ __nv_bfloat16 g_qw_hi[2048 * 2048], g_qw_lo[2048 * 2048];
__device__ __nv_bfloat16 g_kw_hi[512 * 2048],  g_kw_lo[512 * 2048];
__device__ __nv_bfloat16 g_vw_hi[512 * 2048],  g_vw_lo[512 * 2048];
__device__ __nv_bfloat16 g_ow_hi[2048 * 2048], g_ow_lo[2048 * 2048];
__device__ __nv_bfloat16 g_gw_hi[5632 * 2048], g_gw_lo[5632 * 2048];
__device__ __nv_bfloat16 g_uw_hi[5632 * 2048], g_uw_lo[5632 * 2048];
__device__ __nv_bfloat16 g_dw_hi[2048 * 5632], g_dw_lo[2048 * 5632];

// -------------------- helpers --------------------
__device__ __forceinline__ uint32_t smem_u32(const void* p) {
    return (uint32_t)__cvta_generic_to_shared(p);
}

#define LDSM_X4(r0, r1, r2, r3, addr)                                          \
    asm volatile("ldmatrix.sync.aligned.m8n8.x4.shared.b16 {%0,%1,%2,%3}, [%4];" \
                 : "=r"(r0), "=r"(r1), "=r"(r2), "=r"(r3) : "r"(addr))

#define MMA_BF16(ac, ar, br)                                                   \
    asm volatile(                                                              \
        "mma.sync.aligned.m16n8k16.row.col.f32.bf16.bf16.f32 "                 \
        "{%0,%1,%2,%3},{%4,%5,%6,%7},{%8,%9},{%0,%1,%2,%3};"                   \
        : "+f"((ac)[0]), "+f"((ac)[1]), "+f"((ac)[2]), "+f"((ac)[3])           \
        : "r"((ar)[0]), "r"((ar)[1]), "r"((ar)[2]), "r"((ar)[3]),              \
          "r"((br)[0]), "r"((br)[1]))

#define CP_ASYNC16(dst, src)                                                   \
    asm volatile("cp.async.cg.shared.global [%0], [%1], 16;" :: "r"(dst), "l"(src))
#define CP_COMMIT() asm volatile("cp.async.commit_group;")
#define CP_WAIT1()  asm volatile("cp.async.wait_group 1;")

// -------------------- stage loader --------------------
// Stage (32KB): [Ahi 8K][Alo 8K][Bhi 8K][Blo 8K]. 128 rows x 64B (32 bf16).
// Swizzle: column byte (bits 4-5) XOR (row&3)<<4.
__device__ __forceinline__ void load_stage(
    uint32_t sb, int kc, int tid, int m0, int n0, int K,
    const __nv_bfloat16* __restrict__ Ahi, const __nv_bfloat16* __restrict__ Alo,
    const __nv_bfloat16* __restrict__ Bhi, const __nv_bfloat16* __restrict__ Blo)
{
    const int kb = kc * 32;
#pragma unroll
    for (int i = 0; i < 2; i++) {
        int f = tid + i * 256;           // 512 x 16B chunks per buffer
        int r = f >> 2, c = f & 3;
        uint32_t off = (uint32_t)(r * 64) + (uint32_t)((c * 16) ^ ((r & 3) << 4));
        size_t ga = (size_t)(m0 + r) * K + kb + c * 8;
        size_t gb = (size_t)(n0 + r) * K + kb + c * 8;
        CP_ASYNC16(sb + off,         Ahi + ga);
        CP_ASYNC16(sb + 8192 + off,  Alo + ga);
        CP_ASYNC16(sb + 16384 + off, Bhi + gb);
        CP_ASYNC16(sb + 24576 + off, Blo + gb);
    }
}

// -------------------- HMMA split-bf16 GEMM --------------------
// C[M,N] = (Ahi+Alo)[M,K] @ (Bhi+Blo)[N,K]^T (+ epilogue), fp32 out.
// BM=BN=128, BK=32, 3-stage cp.async. 8 warps, each 32(m)x64(n).
// EPI: 0 none, 1 +aux[row], 2 +aux[row*N+col]
template <int EPI>
__global__ __launch_bounds__(256, 2) void bgemm(
    const __nv_bfloat16* __restrict__ Ahi, const __nv_bfloat16* __restrict__ Alo,
    const __nv_bfloat16* __restrict__ Bhi, const __nv_bfloat16* __restrict__ Blo,
    float* __restrict__ C, const float* __restrict__ aux,
    int M, int N, int K)
{
    extern __shared__ char dsm[];
    const int tid = threadIdx.x;
    const int wid = tid >> 5, lid = tid & 31;
    const int wm = wid & 3, wn = wid >> 2;
    const int m0 = blockIdx.y * 128;
    const int n0 = blockIdx.x * 128;
    const uint32_t sbase = smem_u32(dsm);

    // ldmatrix per-lane addressing (swizzle applied to FULL column byte)
    const int arow = wm * 32 + (lid & 7) + ((lid >> 3) & 1) * 8;   // + mt*16
    const uint32_t a_base = (uint32_t)(arow * 64);
    const uint32_t a_sw = (uint32_t)((arow & 3) << 4);
    const uint32_t a_k = (uint32_t)((lid >> 4) & 1) * 16;          // bytes

    const int brow = wn * 64 + (lid & 7) + ((lid >> 4) & 1) * 8;   // + p*16
    const uint32_t b_base = (uint32_t)(brow * 64);
    const uint32_t b_sw = (uint32_t)((brow & 3) << 4);
    const uint32_t b_k = (uint32_t)((lid >> 3) & 1) * 16;          // bytes

    float acc[2][8][4];
#pragma unroll
    for (int mt = 0; mt < 2; mt++)
#pragma unroll
        for (int nt = 0; nt < 8; nt++)
#pragma unroll
            for (int e = 0; e < 4; e++) acc[mt][nt][e] = 0.f;

    const int NK = K / 32;
    load_stage(sbase, 0, tid, m0, n0, K, Ahi, Alo, Bhi, Blo);
    CP_COMMIT();
    load_stage(sbase + 32768, 1, tid, m0, n0, K, Ahi, Alo, Bhi, Blo);
    CP_COMMIT();

    for (int kc = 0; kc < NK; kc++) {
        CP_WAIT1();
        __syncthreads();
        if (kc + 2 < NK)
            load_stage(sbase + (uint32_t)((kc + 2) % 3) * 32768, kc + 2, tid,
                       m0, n0, K, Ahi, Alo, Bhi, Blo);
        CP_COMMIT();

        const uint32_t st = sbase + (uint32_t)(kc % 3) * 32768;
#pragma unroll
        for (int ks = 0; ks < 2; ks++) {
            const uint32_t ako = (a_k + (uint32_t)ks * 32) ^ a_sw;
            const uint32_t bko = (b_k + (uint32_t)ks * 32) ^ b_sw;
            uint32_t ah[2][4], al[2][4], bb[8][2];
#pragma unroll
            for (int mt = 0; mt < 2; mt++) {
                LDSM_X4(ah[mt][0], ah[mt][1], ah[mt][2], ah[mt][3],
                        st + a_base + (uint32_t)mt * 1024 + ako);
                LDSM_X4(al[mt][0], al[mt][1], al[mt][2], al[mt][3],
                        st + 8192 + a_base + (uint32_t)mt * 1024 + ako);
            }
#pragma unroll
            for (int p = 0; p < 4; p++) {
                LDSM_X4(bb[2*p][0], bb[2*p][1], bb[2*p+1][0], bb[2*p+1][1],
                        st + 16384 + b_base + (uint32_t)p * 1024 + bko);
            }
#pragma unroll
            for (int nt = 0; nt < 8; nt++)
#pragma unroll
                for (int mt = 0; mt < 2; mt++)
                    MMA_BF16(acc[mt][nt], ah[mt], bb[nt]);
#pragma unroll
            for (int nt = 0; nt < 8; nt++)
#pragma unroll
                for (int mt = 0; mt < 2; mt++)
                    MMA_BF16(acc[mt][nt], al[mt], bb[nt]);
#pragma unroll
            for (int p = 0; p < 4; p++) {
                LDSM_X4(bb[2*p][0], bb[2*p][1], bb[2*p+1][0], bb[2*p+1][1],
                        st + 24576 + b_base + (uint32_t)p * 1024 + bko);
            }
#pragma unroll
            for (int nt = 0; nt < 8; nt++)
#pragma unroll
                for (int mt = 0; mt < 2; mt++)
                    MMA_BF16(acc[mt][nt], ah[mt], bb[nt]);
        }
    }

    // Epilogue: direct fp32 stores (float2 per mma tile fragment)
    const int grow0 = m0 + wm * 32 + (lid >> 2);
    const int gcol0 = n0 + wn * 64 + (lid & 3) * 2;
#pragma unroll
    for (int mt = 0; mt < 2; mt++) {
#pragma unroll
        for (int nt = 0; nt < 8; nt++) {
            int r0 = grow0 + mt * 16;
            int c0 = gcol0 + nt * 8;
            float2 v0 = make_float2(acc[mt][nt][0], acc[mt][nt][1]);
            float2 v1 = make_float2(acc[mt][nt][2], acc[mt][nt][3]);
            if (EPI == 1) {
                float b0 = aux[r0], b1 = aux[r0 + 8];
                v0.x += b0; v0.y += b0; v1.x += b1; v1.y += b1;
            }
            if (EPI == 2) {
                const float2 a0 = *(const float2*)(aux + (size_t)r0 * N + c0);
                const float2 a1 = *(const float2*)(aux + (size_t)(r0 + 8) * N + c0);
                v0.x += a0.x; v0.y += a0.y; v1.x += a1.x; v1.y += a1.y;
            }
            *(float2*)(C + (size_t)r0 * N + c0) = v0;
            *(float2*)(C + (size_t)(r0 + 8) * N + c0) = v1;
        }
    }
}

// -------------------- conversion kernels --------------------
__global__ void split_kernel(const float* __restrict__ x,
                             __nv_bfloat16* __restrict__ hi,
                             __nv_bfloat16* __restrict__ lo, int n4)
{
    int i = blockIdx.x * 256 + threadIdx.x;
    if (i < n4) {
        float4 v = ((const float4*)x)[i];
        __nv_bfloat16 h0 = __float2bfloat16(v.x), h1 = __float2bfloat16(v.y);
        __nv_bfloat16 h2 = __float2bfloat16(v.z), h3 = __float2bfloat16(v.w);
        __nv_bfloat162 ha; ha.x = h0; ha.y = h1;
        __nv_bfloat162 hb; hb.x = h2; hb.y = h3;
        ((__nv_bfloat162*)hi)[i * 2]     = ha;
        ((__nv_bfloat162*)hi)[i * 2 + 1] = hb;
        __nv_bfloat162 la, lb;
        la.x = __float2bfloat16(v.x - __bfloat162float(h0));
        la.y = __float2bfloat16(v.y - __bfloat162float(h1));
        lb.x = __float2bfloat16(v.z - __bfloat162float(h2));
        lb.y = __float2bfloat16(v.w - __bfloat162float(h3));
        ((__nv_bfloat162*)lo)[i * 2]     = la;
        ((__nv_bfloat162*)lo)[i * 2 + 1] = lb;
    }
}

// hiT[c][r] = x[r][c]
__global__ void transpose_split(const float* __restrict__ x,
                                __nv_bfloat16* __restrict__ hiT,
                                __nv_bfloat16* __restrict__ loT, int R, int C)
{
    __shared__ float t[32][33];
    int c0 = blockIdx.x * 32, r0 = blockIdx.y * 32;
    for (int i = threadIdx.y; i < 32; i += 8)
        t[i][threadIdx.x] = x[(size_t)(r0 + i) * C + c0 + threadIdx.x];
    __syncthreads();
    for (int i = threadIdx.y; i < 32; i += 8) {
        float v = t[threadIdx.x][i];
        __nv_bfloat16 h = __float2bfloat16(v);
        size_t o = (size_t)(c0 + i) * R + r0 + threadIdx.x;
        hiT[o] = h;
        loT[o] = __float2bfloat16(v - __bfloat162float(h));
    }
}

// -------------------- RMSNorm (fused split output) --------------------
__global__ void rmsnorm_kernel(const float* __restrict__ x,
                               const float* __restrict__ w,
                               float* __restrict__ y,
                               __nv_bfloat16* __restrict__ yhi,
                               __nv_bfloat16* __restrict__ ylo)
{
    const int row = blockIdx.x;
    const float* xr = x + (size_t)row * 2048;
    float ss = 0.f;
    for (int i = threadIdx.x; i < 2048; i += 256) { float v = xr[i]; ss += v * v; }
    __shared__ float red[256];
    red[threadIdx.x] = ss;
    __syncthreads();
    for (int s = 128; s > 0; s >>= 1) {
        if (threadIdx.x < s) red[threadIdx.x] += red[threadIdx.x + s];
        __syncthreads();
    }
    __shared__ float inv;
    if (threadIdx.x == 0) inv = rsqrtf(red[0] * (1.f / 2048.f) + 1e-6f);
    __syncthreads();
    float iv = inv;
    for (int i = threadIdx.x; i < 2048; i += 256) {
        float v = xr[i] * iv * w[i];
        size_t o = (size_t)row * 2048 + i;
        y[o] = v;
        __nv_bfloat16 h = __float2bfloat16(v);
        yhi[o] = h;
        ylo[o] = __float2bfloat16(v - __bfloat162float(h));
    }
}

// -------------------- SwiGLU (split output) --------------------
__global__ void swiglu_split(const float* __restrict__ g, const float* __restrict__ u,
                             __nv_bfloat16* __restrict__ hi, __nv_bfloat16* __restrict__ lo,
                             int n)
{
    int i = blockIdx.x * blockDim.x + threadIdx.x;
    if (i < n) {
        float x = g[i];
        float v = (x / (1.f + __expf(-x))) * u[i];
        __nv_bfloat16 h = __float2bfloat16(v);
        hi[i] = h;
        lo[i] = __float2bfloat16(v - __bfloat162float(h));
    }
}

// -------------------- fp32 flash attention --------------------
__global__ __launch_bounds__(256) void attn_kernel(
    const float* __restrict__ Q, const float* __restrict__ K,
    const float* __restrict__ V, float* __restrict__ O)
{
    __shared__ float Qs[64][68];
    __shared__ float Ks[32][68];
    __shared__ float Vs[32][68];
    __shared__ float Ss[64][36];
    __shared__ float mrow[64], lrow[64], frow[64];

    const int tid = threadIdx.x;
    const int q0 = blockIdx.x * 64;
    const int head = blockIdx.y;
    const int kvoff = (head >> 2) * 64;

#pragma unroll
    for (int i = 0; i < 4; i++) {
        int flat = tid + i * 256;
        int r = flat >> 4;
        int c = (flat & 15) << 2;
        float4 v = *(const float4*)(Q + (size_t)(q0 + r) * 2048 + head * 64 + c);
        *(float4*)&Qs[r][c] = v;
    }
    if (tid < 64) { mrow[tid] = -1e30f; lrow[tid] = 0.f; }

    const int qr0 = (tid >> 4) * 4;
    const int kc0 = (tid & 15) * 2;
    const int dc0 = (tid & 15) * 4;

    float acc[4][4];
#pragma unroll
    for (int i = 0; i < 4; i++)
#pragma unroll
        for (int j = 0; j < 4; j++) acc[i][j] = 0.f;

    for (int t0 = 0; t0 < 3072; t0 += 32) {
        __syncthreads();
#pragma unroll
        for (int i = 0; i < 2; i++) {
            int flat = tid + i * 256;
            int r = flat >> 4;
            int c = (flat & 15) << 2;
            *(float4*)&Ks[r][c] = *(const float4*)(K + (size_t)(t0 + r) * 512 + kvoff + c);
            *(float4*)&Vs[r][c] = *(const float4*)(V + (size_t)(t0 + r) * 512 + kvoff + c);
        }
        __syncthreads();

        float s[4][2];
#pragma unroll
        for (int i = 0; i < 4; i++) { s[i][0] = 0.f; s[i][1] = 0.f; }
#pragma unroll
        for (int d = 0; d < 64; d++) {
            float qv[4], kv[2];
#pragma unroll
            for (int i = 0; i < 4; i++) qv[i] = Qs[qr0 + i][d];
            kv[0] = Ks[kc0 + 0][d];
            kv[1] = Ks[kc0 + 1][d];
#pragma unroll
            for (int i = 0; i < 4; i++) {
                s[i][0] += qv[i] * kv[0];
                s[i][1] += qv[i] * kv[1];
            }
        }
#pragma unroll
        for (int i = 0; i < 4; i++) {
            Ss[qr0 + i][kc0 + 0] = s[i][0] * 0.125f;
            Ss[qr0 + i][kc0 + 1] = s[i][1] * 0.125f;
        }
        __syncthreads();

        if (tid < 64) {
            int r = tid;
            float mt = mrow[r];
            for (int c = 0; c < 32; c++) mt = fmaxf(mt, Ss[r][c]);
            float f = __expf(mrow[r] - mt);
            float l = lrow[r] * f;
            for (int c = 0; c < 32; c++) {
                float p = __expf(Ss[r][c] - mt);
                Ss[r][c] = p;
                l += p;
            }
            mrow[r] = mt; lrow[r] = l; frow[r] = f;
        }
        __syncthreads();

#pragma unroll
        for (int i = 0; i < 4; i++) {
            float f = frow[qr0 + i];
#pragma unroll
            for (int j = 0; j < 4; j++) acc[i][j] *= f;
        }
#pragma unroll
        for (int kc = 0; kc < 32; kc++) {
            float p[4], v[4];
#pragma unroll
            for (int i = 0; i < 4; i++) p[i] = Ss[qr0 + i][kc];
#pragma unroll
            for (int j = 0; j < 4; j++) v[j] = Vs[kc][dc0 + j];
#pragma unroll
            for (int i = 0; i < 4; i++)
#pragma unroll
                for (int j = 0; j < 4; j++) acc[i][j] += p[i] * v[j];
        }
    }

#pragma unroll
    for (int i = 0; i < 4; i++) {
        float il = 1.f / lrow[qr0 + i];
#pragma unroll
        for (int j = 0; j < 4; j++)
            O[(size_t)(q0 + qr0 + i) * 2048 + head * 64 + dc0 + j] = acc[i][j] * il;
    }
}

// -------------------- orchestration --------------------
static const int SMEM_DYN = 3 * 32768;   // 96KB: 3 stages

extern "C" void kernel_launch(void* const* d_in, const int* in_sizes, int n_in,
                              void* d_out, int out_size)
{
    (void)in_sizes; (void)n_in; (void)out_size;
    const float* hidden      = (const float*)d_in[0];
    const float* comp_w      = (const float*)d_in[1];
    const float* comp_b      = (const float*)d_in[2];
    const float* q_w         = (const float*)d_in[3];
    const float* k_w         = (const float*)d_in[4];
    const float* v_w         = (const float*)d_in[5];
    const float* o_w         = (const float*)d_in[6];
    const float* attn_norm_w = (const float*)d_in[7];
    const float* mlp_norm_w  = (const float*)d_in[8];
    const float* gate_w      = (const float*)d_in[9];
    const float* up_w        = (const float*)d_in[10];
    const float* down_w      = (const float*)d_in[11];
    float* out = (float*)d_out;

    cudaFuncSetAttribute(bgemm<0>, cudaFuncAttributeMaxDynamicSharedMemorySize, SMEM_DYN);
    cudaFuncSetAttribute(bgemm<1>, cudaFuncAttributeMaxDynamicSharedMemorySize, SMEM_DYN);
    cudaFuncSetAttribute(bgemm<2>, cudaFuncAttributeMaxDynamicSharedMemorySize, SMEM_DYN);

    float *compressed, *ct, *q, *k, *v, *attno, *gate, *up;
    cudaGetSymbolAddress((void**)&compressed, g_compressed);
    cudaGetSymbolAddress((void**)&ct,         g_ct);
    cudaGetSymbolAddress((void**)&q,          g_q);
    cudaGetSymbolAddress((void**)&k,          g_k);
    cudaGetSymbolAddress((void**)&v,          g_v);
    cudaGetSymbolAddress((void**)&attno,      g_attno);
    cudaGetSymbolAddress((void**)&gate,       g_gate);
    cudaGetSymbolAddress((void**)&up,         g_up);

    __nv_bfloat16 *res_hi, *res_lo, *ct_hi, *ct_lo, *ao_hi, *ao_lo, *ga_hi, *ga_lo,
                  *hT_hi, *hT_lo, *cw_hi, *cw_lo, *qw_hi, *qw_lo, *kw_hi, *kw_lo,
                  *vw_hi, *vw_lo, *ow_hi, *ow_lo, *gw_hi, *gw_lo, *uw_hi, *uw_lo,
                  *dw_hi, *dw_lo;
    cudaGetSymbolAddress((void**)&res_hi, g_res_hi); cudaGetSymbolAddress((void**)&res_lo, g_res_lo);
    cudaGetSymbolAddress((void**)&ct_hi,  g_ct_hi);  cudaGetSymbolAddress((void**)&ct_lo,  g_ct_lo);
    cudaGetSymbolAddress((void**)&ao_hi,  g_ao_hi);  cudaGetSymbolAddress((void**)&ao_lo,  g_ao_lo);
    cudaGetSymbolAddress((void**)&ga_hi,  g_ga_hi);  cudaGetSymbolAddress((void**)&ga_lo,  g_ga_lo);
    cudaGetSymbolAddress((void**)&hT_hi,  g_hT_hi);  cudaGetSymbolAddress((void**)&hT_lo,  g_hT_lo);
    cudaGetSymbolAddress((void**)&cw_hi,  g_cw_hi);  cudaGetSymbolAddress((void**)&cw_lo,  g_cw_lo);
    cudaGetSymbolAddress((void**)&qw_hi,  g_qw_hi);  cudaGetSymbolAddress((void**)&qw_lo,  g_qw_lo);
    cudaGetSymbolAddress((void**)&kw_hi,  g_kw_hi);  cudaGetSymbolAddress((void**)&kw_lo,  g_kw_lo);
    cudaGetSymbolAddress((void**)&vw_hi,  g_vw_hi);  cudaGetSymbolAddress((void**)&vw_lo,  g_vw_lo);
    cudaGetSymbolAddress((void**)&ow_hi,  g_ow_hi);  cudaGetSymbolAddress((void**)&ow_lo,  g_ow_lo);
    cudaGetSymbolAddress((void**)&gw_hi,  g_gw_hi);  cudaGetSymbolAddress((void**)&gw_lo,  g_gw_lo);
    cudaGetSymbolAddress((void**)&uw_hi,  g_uw_hi);  cudaGetSymbolAddress((void**)&uw_lo,  g_uw_lo);
    cudaGetSymbolAddress((void**)&dw_hi,  g_dw_hi);  cudaGetSymbolAddress((void**)&dw_lo,  g_dw_lo);

    auto split = [&](const float* src, __nv_bfloat16* hi, __nv_bfloat16* lo, int n) {
        int n4 = n / 4;
        split_kernel<<<(n4 + 255) / 256, 256>>>(src, hi, lo, n4);
    };

    // weight conversions
    split(comp_w, cw_hi, cw_lo, 1024 * 2048);
    split(q_w,    qw_hi, qw_lo, 2048 * 2048);
    split(k_w,    kw_hi, kw_lo, 512 * 2048);
    split(v_w,    vw_hi, vw_lo, 512 * 2048);
    split(o_w,    ow_hi, ow_lo, 2048 * 2048);
    split(gate_w, gw_hi, gw_lo, 5632 * 2048);
    split(up_w,   uw_hi, uw_lo, 5632 * 2048);
    split(down_w, dw_hi, dw_lo, 2048 * 5632);
    transpose_split<<<dim3(64, 64), dim3(32, 8)>>>(hidden, hT_hi, hT_lo, 2048, 2048);
    split(hidden, res_hi, res_lo, 2048 * 2048);

    // compressed = comp_w @ hidden + comp_b
    bgemm<1><<<dim3(16, 8), 256, SMEM_DYN>>>(cw_hi, cw_lo, hT_hi, hT_lo,
                                             compressed, comp_b, 1024, 2048, 2048);

    for (int layer = 0; layer < 2; layer++) {
        split(compressed, res_hi + 2048 * 2048, res_lo + 2048 * 2048, 1024 * 2048);
        rmsnorm_kernel<<<1024, 256>>>(compressed, attn_norm_w, ct, ct_hi, ct_lo);

        bgemm<0><<<dim3(16, 8),  256, SMEM_DYN>>>(ct_hi, ct_lo, qw_hi, qw_lo, q, nullptr, 1024, 2048, 2048);
        bgemm<0><<<dim3(4, 24),  256, SMEM_DYN>>>(res_hi, res_lo, kw_hi, kw_lo, k, nullptr, 3072, 512, 2048);
        bgemm<0><<<dim3(4, 24),  256, SMEM_DYN>>>(res_hi, res_lo, vw_hi, vw_lo, v, nullptr, 3072, 512, 2048);

        attn_kernel<<<dim3(16, 32), 256>>>(q, k, v, attno);

        split(attno, ao_hi, ao_lo, 1024 * 2048);
        bgemm<2><<<dim3(16, 8), 256, SMEM_DYN>>>(ao_hi, ao_lo, ow_hi, ow_lo,
                                                 compressed, ct, 1024, 2048, 2048);

        rmsnorm_kernel<<<1024, 256>>>(compressed, mlp_norm_w, ct, ct_hi, ct_lo);

        bgemm<0><<<dim3(44, 8), 256, SMEM_DYN>>>(ct_hi, ct_lo, gw_hi, gw_lo, gate, nullptr, 1024, 5632, 2048);
        bgemm<0><<<dim3(44, 8), 256, SMEM_DYN>>>(ct_hi, ct_lo, uw_hi, uw_lo, up, nullptr, 1024, 5632, 2048);

        swiglu_split<<<(1024 * 5632 + 255) / 256, 256>>>(gate, up, ga_hi, ga_lo, 1024 * 5632);

        float* dst = (layer == 1) ? out : compressed;
        bgemm<2><<<dim3(16, 8), 256, SMEM_DYN>>>(ga_hi, ga_lo, dw_hi, dw_lo,
                                                 dst, ct, 1024, 2048, 5632);
    }
}

// round 5
// speedup vs baseline: 3.2435x; 1.5810x over previous
#include <cuda_runtime.h>
#include <cuda_bf16.h>
#include <cstdint>
#include <math.h>

// ===========================================================================
// S=2048, H=2048, COMP=1024, T=3072, KV_DIM=512, FF=5632, NH=32, NKV=8,
// HD=64, DEPTH=2. All mma.sync.m16n8k16 bf16 with hi/lo 3-product split
// (GEMMs AND attention). cp.async pipelines everywhere.
// ===========================================================================

// -------------------- device-global scratch (no allocs) --------------------
__device__ float g_compressed[1024 * 2048];
__device__ float g_ct[1024 * 2048];
__device__ float g_gate[1024 * 5632];
__device__ float g_up[1024 * 5632];

__device__ __nv_bfloat16 g_res_hi[3072 * 2048], g_res_lo[3072 * 2048];
__device__ __nv_bfloat16 g_ct_hi[1024 * 2048], g_ct_lo[1024 * 2048];
__device__ __nv_bfloat16 g_ao_hi[1024 * 2048], g_ao_lo[1024 * 2048];
__device__ __nv_bfloat16 g_ga_hi[1024 * 5632], g_ga_lo[1024 * 5632];
__device__ __nv_bfloat16 g_hT_hi[2048 * 2048], g_hT_lo[2048 * 2048];

__device__ __nv_bfloat16 g_q_hi[1024 * 2048], g_q_lo[1024 * 2048];
__device__ __nv_bfloat16 g_k_hi[3072 * 512],  g_k_lo[3072 * 512];
__device__ __nv_bfloat16 g_v_hi[3072 * 512],  g_v_lo[3072 * 512];

__device__ __nv_bfloat16 g_cw_hi[1024 * 2048], g_cw_lo[1024 * 2048];
__device__ __nv_bfloat16 g_qw_hi[2048 * 2048], g_qw_lo[2048 * 2048];
__device__ __nv_bfloat16 g_kw_hi[512 * 2048],  g_kw_lo[512 * 2048];
__device__ __nv_bfloat16 g_vw_hi[512 * 2048],  g_vw_lo[512 * 2048];
__device__ __nv_bfloat16 g_ow_hi[2048 * 2048], g_ow_lo[2048 * 2048];
__device__ __nv_bfloat16 g_gw_hi[5632 * 2048], g_gw_lo[5632 * 2048];
__device__ __nv_bfloat16 g_uw_hi[5632 * 2048], g_uw_lo[5632 * 2048];
__device__ __nv_bfloat16 g_dw_hi[2048 * 5632], g_dw_lo[2048 * 5632];

// -------------------- helpers --------------------
__device__ __forceinline__ uint32_t smem_u32(const void* p) {
    return (uint32_t)__cvta_generic_to_shared(p);
}

#define LDSM_X4(r0, r1, r2, r3, addr)                                          \
    asm volatile("ldmatrix.sync.aligned.m8n8.x4.shared.b16 {%0,%1,%2,%3}, [%4];" \
                 : "=r"(r0), "=r"(r1), "=r"(r2), "=r"(r3) : "r"(addr))
#define LDSM_X4_T(r0, r1, r2, r3, addr)                                        \
    asm volatile("ldmatrix.sync.aligned.m8n8.x4.trans.shared.b16 {%0,%1,%2,%3}, [%4];" \
                 : "=r"(r0), "=r"(r1), "=r"(r2), "=r"(r3) : "r"(addr))

#define MMA_BF16(ac, ar, br)                                                   \
    asm volatile(                                                              \
        "mma.sync.aligned.m16n8k16.row.col.f32.bf16.bf16.f32 "                 \
        "{%0,%1,%2,%3},{%4,%5,%6,%7},{%8,%9},{%0,%1,%2,%3};"                   \
        : "+f"((ac)[0]), "+f"((ac)[1]), "+f"((ac)[2]), "+f"((ac)[3])           \
        : "r"((ar)[0]), "r"((ar)[1]), "r"((ar)[2]), "r"((ar)[3]),              \
          "r"((br)[0]), "r"((br)[1]))

#define CP_ASYNC16(dst, src)                                                   \
    asm volatile("cp.async.cg.shared.global [%0], [%1], 16;" :: "r"(dst), "l"(src))
#define CP_COMMIT() asm volatile("cp.async.commit_group;")
#define CP_WAIT1()  asm volatile("cp.async.wait_group 1;")

__device__ __forceinline__ uint32_t pack_bf2(float x, float y) {
    __nv_bfloat162 h = __floats2bfloat162_rn(x, y);
    return *(uint32_t*)&h;
}

// ==================== HMMA split-bf16 GEMM ====================
// C = (Ahi+Alo)[M,K] @ (Bhi+Blo)[N,K]^T (+epi). BM=BN=128, BK=32, 3-stage.
// EPI: 0 none, 1 +aux[row], 2 +aux[row*N+col]
// OUT: 0 fp32 C; 1 bf16 hi/lo split into Chi/Clo
__device__ __forceinline__ void load_stage(
    uint32_t sb, int kc, int tid, int m0, int n0, int K,
    const __nv_bfloat16* __restrict__ Ahi, const __nv_bfloat16* __restrict__ Alo,
    const __nv_bfloat16* __restrict__ Bhi, const __nv_bfloat16* __restrict__ Blo)
{
    const int kb = kc * 32;
#pragma unroll
    for (int i = 0; i < 2; i++) {
        int f = tid + i * 256;
        int r = f >> 2, c = f & 3;
        uint32_t off = (uint32_t)(r * 64) + (uint32_t)((c * 16) ^ ((r & 3) << 4));
        size_t ga = (size_t)(m0 + r) * K + kb + c * 8;
        size_t gb = (size_t)(n0 + r) * K + kb + c * 8;
        CP_ASYNC16(sb + off,         Ahi + ga);
        CP_ASYNC16(sb + 8192 + off,  Alo + ga);
        CP_ASYNC16(sb + 16384 + off, Bhi + gb);
        CP_ASYNC16(sb + 24576 + off, Blo + gb);
    }
}

template <int EPI, int OUT>
__global__ __launch_bounds__(256, 2) void bgemm(
    const __nv_bfloat16* __restrict__ Ahi, const __nv_bfloat16* __restrict__ Alo,
    const __nv_bfloat16* __restrict__ Bhi, const __nv_bfloat16* __restrict__ Blo,
    float* __restrict__ C, const float* __restrict__ aux,
    __nv_bfloat16* __restrict__ Chi, __nv_bfloat16* __restrict__ Clo,
    int M, int N, int K)
{
    extern __shared__ char dsm[];
    const int tid = threadIdx.x;
    const int wid = tid >> 5, lid = tid & 31;
    const int wm = wid & 3, wn = wid >> 2;
    const int m0 = blockIdx.y * 128;
    const int n0 = blockIdx.x * 128;
    const uint32_t sbase = smem_u32(dsm);

    const int arow = wm * 32 + (lid & 7) + ((lid >> 3) & 1) * 8;
    const uint32_t a_base = (uint32_t)(arow * 64);
    const uint32_t a_sw = (uint32_t)((arow & 3) << 4);
    const uint32_t a_k = (uint32_t)((lid >> 4) & 1) * 16;

    const int brow = wn * 64 + (lid & 7) + ((lid >> 4) & 1) * 8;
    const uint32_t b_base = (uint32_t)(brow * 64);
    const uint32_t b_sw = (uint32_t)((brow & 3) << 4);
    const uint32_t b_k = (uint32_t)((lid >> 3) & 1) * 16;

    float acc[2][8][4];
#pragma unroll
    for (int mt = 0; mt < 2; mt++)
#pragma unroll
        for (int nt = 0; nt < 8; nt++)
#pragma unroll
            for (int e = 0; e < 4; e++) acc[mt][nt][e] = 0.f;

    const int NK = K / 32;
    load_stage(sbase, 0, tid, m0, n0, K, Ahi, Alo, Bhi, Blo);
    CP_COMMIT();
    load_stage(sbase + 32768, 1, tid, m0, n0, K, Ahi, Alo, Bhi, Blo);
    CP_COMMIT();

    for (int kc = 0; kc < NK; kc++) {
        CP_WAIT1();
        __syncthreads();
        if (kc + 2 < NK)
            load_stage(sbase + (uint32_t)((kc + 2) % 3) * 32768, kc + 2, tid,
                       m0, n0, K, Ahi, Alo, Bhi, Blo);
        CP_COMMIT();

        const uint32_t st = sbase + (uint32_t)(kc % 3) * 32768;
#pragma unroll
        for (int ks = 0; ks < 2; ks++) {
            const uint32_t ako = (a_k + (uint32_t)ks * 32) ^ a_sw;
            const uint32_t bko = (b_k + (uint32_t)ks * 32) ^ b_sw;
            uint32_t ah[2][4], al[2][4], bb[8][2];
#pragma unroll
            for (int mt = 0; mt < 2; mt++) {
                LDSM_X4(ah[mt][0], ah[mt][1], ah[mt][2], ah[mt][3],
                        st + a_base + (uint32_t)mt * 1024 + ako);
                LDSM_X4(al[mt][0], al[mt][1], al[mt][2], al[mt][3],
                        st + 8192 + a_base + (uint32_t)mt * 1024 + ako);
            }
#pragma unroll
            for (int p = 0; p < 4; p++) {
                LDSM_X4(bb[2*p][0], bb[2*p][1], bb[2*p+1][0], bb[2*p+1][1],
                        st + 16384 + b_base + (uint32_t)p * 1024 + bko);
            }
#pragma unroll
            for (int nt = 0; nt < 8; nt++)
#pragma unroll
                for (int mt = 0; mt < 2; mt++)
                    MMA_BF16(acc[mt][nt], ah[mt], bb[nt]);
#pragma unroll
            for (int nt = 0; nt < 8; nt++)
#pragma unroll
                for (int mt = 0; mt < 2; mt++)
                    MMA_BF16(acc[mt][nt], al[mt], bb[nt]);
#pragma unroll
            for (int p = 0; p < 4; p++) {
                LDSM_X4(bb[2*p][0], bb[2*p][1], bb[2*p+1][0], bb[2*p+1][1],
                        st + 24576 + b_base + (uint32_t)p * 1024 + bko);
            }
#pragma unroll
            for (int nt = 0; nt < 8; nt++)
#pragma unroll
                for (int mt = 0; mt < 2; mt++)
                    MMA_BF16(acc[mt][nt], ah[mt], bb[nt]);
        }
    }

    const int grow0 = m0 + wm * 32 + (lid >> 2);
    const int gcol0 = n0 + wn * 64 + (lid & 3) * 2;
#pragma unroll
    for (int mt = 0; mt < 2; mt++) {
#pragma unroll
        for (int nt = 0; nt < 8; nt++) {
            int r0 = grow0 + mt * 16;
            int c0 = gcol0 + nt * 8;
            float2 v0 = make_float2(acc[mt][nt][0], acc[mt][nt][1]);
            float2 v1 = make_float2(acc[mt][nt][2], acc[mt][nt][3]);
            if (EPI == 1) {
                float b0 = aux[r0], b1 = aux[r0 + 8];
                v0.x += b0; v0.y += b0; v1.x += b1; v1.y += b1;
            }
            if (EPI == 2) {
                const float2 a0 = *(const float2*)(aux + (size_t)r0 * N + c0);
                const float2 a1 = *(const float2*)(aux + (size_t)(r0 + 8) * N + c0);
                v0.x += a0.x; v0.y += a0.y; v1.x += a1.x; v1.y += a1.y;
            }
            if (OUT == 0) {
                *(float2*)(C + (size_t)r0 * N + c0) = v0;
                *(float2*)(C + (size_t)(r0 + 8) * N + c0) = v1;
            } else {
                uint32_t h0 = pack_bf2(v0.x, v0.y);
                uint32_t h1 = pack_bf2(v1.x, v1.y);
                *(uint32_t*)(Chi + (size_t)r0 * N + c0) = h0;
                *(uint32_t*)(Chi + (size_t)(r0 + 8) * N + c0) = h1;
                __nv_bfloat162 hh0 = *(__nv_bfloat162*)&h0;
                __nv_bfloat162 hh1 = *(__nv_bfloat162*)&h1;
                uint32_t l0 = pack_bf2(v0.x - __bfloat162float(hh0.x),
                                       v0.y - __bfloat162float(hh0.y));
                uint32_t l1 = pack_bf2(v1.x - __bfloat162float(hh1.x),
                                       v1.y - __bfloat162float(hh1.y));
                *(uint32_t*)(Clo + (size_t)r0 * N + c0) = l0;
                *(uint32_t*)(Clo + (size_t)(r0 + 8) * N + c0) = l1;
            }
        }
    }
}

// ==================== HMMA split-bf16 flash attention ====================
// grid (16 q-tiles, 32 heads), 128 threads (4 warps, 16 q-rows each).
// BT=32, triple-buffered cp.async K/V. Output: bf16 hi/lo.
__global__ __launch_bounds__(128, 3) void attn_mma(
    const __nv_bfloat16* __restrict__ Qhi, const __nv_bfloat16* __restrict__ Qlo,
    const __nv_bfloat16* __restrict__ Khi, const __nv_bfloat16* __restrict__ Klo,
    const __nv_bfloat16* __restrict__ Vhi, const __nv_bfloat16* __restrict__ Vlo,
    __nv_bfloat16* __restrict__ Ohi, __nv_bfloat16* __restrict__ Olo)
{
    extern __shared__ char sm[];
    const int tid = threadIdx.x;
    const int wid = tid >> 5, lid = tid & 31;
    const int q0 = blockIdx.x * 64;
    const int head = blockIdx.y;
    const int kvoff = (head >> 2) * 64;
    const uint32_t sb = smem_u32(sm);
    const uint32_t sQh = sb, sQl = sb + 8192;
    const uint32_t sKV = sb + 16384;   // stage st: +st*16384: Kh,Kl,Vh,Vl x 4KB

    // Q tile loads (group 0): 64 rows x 128B, swizzle (r&7)<<4 on 16B chunks
#pragma unroll
    for (int i = 0; i < 4; i++) {
        int f = tid + i * 128;
        int r = f >> 3, c = f & 7;
        uint32_t off = (uint32_t)(r * 128) + (uint32_t)((c * 16) ^ ((r & 7) << 4));
        size_t g = (size_t)(q0 + r) * 2048 + head * 64 + c * 8;
        CP_ASYNC16(sQh + off, Qhi + g);
        CP_ASYNC16(sQl + off, Qlo + g);
    }
    CP_COMMIT();

#define ISSUE_KV(t0, st)                                                       \
    {                                                                          \
        uint32_t s_ = sKV + (uint32_t)(st) * 16384;                            \
        _Pragma("unroll")                                                      \
        for (int i_ = 0; i_ < 2; i_++) {                                       \
            int f_ = tid + i_ * 128;                                           \
            int r_ = f_ >> 3, c_ = f_ & 7;                                     \
            uint32_t o_ = (uint32_t)(r_ * 128) +                               \
                          (uint32_t)((c_ * 16) ^ ((r_ & 7) << 4));             \
            size_t g_ = (size_t)((t0) + r_) * 512 + kvoff + c_ * 8;            \
            CP_ASYNC16(s_ + o_,         Khi + g_);                             \
            CP_ASYNC16(s_ + 4096 + o_,  Klo + g_);                             \
            CP_ASYNC16(s_ + 8192 + o_,  Vhi + g_);                             \
            CP_ASYNC16(s_ + 12288 + o_, Vlo + g_);                             \
        }                                                                      \
    }

    ISSUE_KV(0, 0);  CP_COMMIT();
    ISSUE_KV(32, 1); CP_COMMIT();

    asm volatile("cp.async.wait_group 2;");
    __syncthreads();

    // preload Q fragments (reused for all 96 t-tiles)
    uint32_t qh[4][4], ql[4][4];
    {
        const int ar = (lid & 7) + ((lid >> 3) & 1) * 8;
        const int row = wid * 16 + ar;
        const uint32_t khalf = (uint32_t)((lid >> 4) & 1) * 16;
#pragma unroll
        for (int ks = 0; ks < 4; ks++) {
            uint32_t off = (uint32_t)(row * 128) +
                           ((khalf + (uint32_t)ks * 32) ^ ((uint32_t)(ar & 7) << 4));
            LDSM_X4(qh[ks][0], qh[ks][1], qh[ks][2], qh[ks][3], sQh + off);
            LDSM_X4(ql[ks][0], ql[ks][1], ql[ks][2], ql[ks][3], sQl + off);
        }
    }

    float acc_o[8][4];
#pragma unroll
    for (int d = 0; d < 8; d++)
#pragma unroll
        for (int e = 0; e < 4; e++) acc_o[d][e] = 0.f;
    float mr0 = -1e30f, mr1 = -1e30f, lr0 = 0.f, lr1 = 0.f;

    const int brS = (lid & 7) + ((lid >> 4) & 1) * 8;      // K n-rows
    const uint32_t bkS = (uint32_t)((lid >> 3) & 1) * 16;
    const int trV = (lid & 7) + ((lid >> 3) & 1) * 8;      // V t-rows (trans)
    const uint32_t dkV = (uint32_t)((lid >> 4) & 1) * 16;

    for (int t = 0; t < 96; t++) {
        if (t + 1 < 96) { CP_WAIT1(); } else { asm volatile("cp.async.wait_group 0;"); }
        __syncthreads();
        if (t + 2 < 96) ISSUE_KV((t + 2) * 32, (t + 2) % 3);
        CP_COMMIT();
        const uint32_t st = sKV + (uint32_t)(t % 3) * 16384;

        // ---- S = Q K^T (16 x 32 per warp)
        float s[4][4];
#pragma unroll
        for (int nt = 0; nt < 4; nt++)
#pragma unroll
            for (int e = 0; e < 4; e++) s[nt][e] = 0.f;
#pragma unroll
        for (int ks = 0; ks < 4; ks++) {
            uint32_t bh[4][2], bl[4][2];
#pragma unroll
            for (int p = 0; p < 2; p++) {
                int rr = p * 16 + brS;
                uint32_t off = (uint32_t)(rr * 128) +
                               ((bkS + (uint32_t)ks * 32) ^ ((uint32_t)(rr & 7) << 4));
                LDSM_X4(bh[2*p][0], bh[2*p][1], bh[2*p+1][0], bh[2*p+1][1], st + off);
                LDSM_X4(bl[2*p][0], bl[2*p][1], bl[2*p+1][0], bl[2*p+1][1], st + 4096 + off);
            }
#pragma unroll
            for (int nt = 0; nt < 4; nt++) {
                MMA_BF16(s[nt], qh[ks], bh[nt]);
                MMA_BF16(s[nt], qh[ks], bl[nt]);
                MMA_BF16(s[nt], ql[ks], bh[nt]);
            }
        }

        // ---- online softmax (rows gr=lid>>2 and gr+8)
        float mn0 = mr0, mn1 = mr1;
#pragma unroll
        for (int nt = 0; nt < 4; nt++) {
            s[nt][0] *= 0.125f; s[nt][1] *= 0.125f;
            s[nt][2] *= 0.125f; s[nt][3] *= 0.125f;
            mn0 = fmaxf(mn0, fmaxf(s[nt][0], s[nt][1]));
            mn1 = fmaxf(mn1, fmaxf(s[nt][2], s[nt][3]));
        }
        mn0 = fmaxf(mn0, __shfl_xor_sync(0xffffffffu, mn0, 1));
        mn0 = fmaxf(mn0, __shfl_xor_sync(0xffffffffu, mn0, 2));
        mn1 = fmaxf(mn1, __shfl_xor_sync(0xffffffffu, mn1, 1));
        mn1 = fmaxf(mn1, __shfl_xor_sync(0xffffffffu, mn1, 2));
        float f0 = __expf(mr0 - mn0), f1 = __expf(mr1 - mn1);
        mr0 = mn0; mr1 = mn1;
        float ps0 = 0.f, ps1 = 0.f;
#pragma unroll
        for (int nt = 0; nt < 4; nt++) {
            s[nt][0] = __expf(s[nt][0] - mn0);
            s[nt][1] = __expf(s[nt][1] - mn0);
            s[nt][2] = __expf(s[nt][2] - mn1);
            s[nt][3] = __expf(s[nt][3] - mn1);
            ps0 += s[nt][0] + s[nt][1];
            ps1 += s[nt][2] + s[nt][3];
        }
        lr0 = lr0 * f0 + ps0;
        lr1 = lr1 * f1 + ps1;
#pragma unroll
        for (int d = 0; d < 8; d++) {
            acc_o[d][0] *= f0; acc_o[d][1] *= f0;
            acc_o[d][2] *= f1; acc_o[d][3] *= f1;
        }

        // ---- O += P V (P split hi/lo, V split hi/lo)
#pragma unroll
        for (int j = 0; j < 2; j++) {
            uint32_t ah[4], al[4];
            {
                float p00 = s[2*j][0],   p01 = s[2*j][1];
                float p02 = s[2*j][2],   p03 = s[2*j][3];
                float p10 = s[2*j+1][0], p11 = s[2*j+1][1];
                float p12 = s[2*j+1][2], p13 = s[2*j+1][3];
                ah[0] = pack_bf2(p00, p01); ah[1] = pack_bf2(p02, p03);
                ah[2] = pack_bf2(p10, p11); ah[3] = pack_bf2(p12, p13);
#pragma unroll
                for (int e = 0; e < 4; e++) {
                    __nv_bfloat162 hh = *(__nv_bfloat162*)&ah[e];
                    float x0, x1;
                    if (e == 0) { x0 = p00; x1 = p01; }
                    else if (e == 1) { x0 = p02; x1 = p03; }
                    else if (e == 2) { x0 = p10; x1 = p11; }
                    else { x0 = p12; x1 = p13; }
                    al[e] = pack_bf2(x0 - __bfloat162float(hh.x),
                                     x1 - __bfloat162float(hh.y));
                }
            }
            const int rr = j * 16 + trV;
#pragma unroll
            for (int dp = 0; dp < 4; dp++) {
                uint32_t off = (uint32_t)(rr * 128) +
                               ((dkV + (uint32_t)dp * 32) ^ ((uint32_t)(rr & 7) << 4));
                uint32_t vh[4], vl[4];
                LDSM_X4_T(vh[0], vh[1], vh[2], vh[3], st + 8192 + off);
                LDSM_X4_T(vl[0], vl[1], vl[2], vl[3], st + 12288 + off);
                uint32_t b0h[2] = {vh[0], vh[1]}, b1h[2] = {vh[2], vh[3]};
                uint32_t b0l[2] = {vl[0], vl[1]}, b1l[2] = {vl[2], vl[3]};
                MMA_BF16(acc_o[2*dp],   ah, b0h);
                MMA_BF16(acc_o[2*dp],   ah, b0l);
                MMA_BF16(acc_o[2*dp],   al, b0h);
                MMA_BF16(acc_o[2*dp+1], ah, b1h);
                MMA_BF16(acc_o[2*dp+1], ah, b1l);
                MMA_BF16(acc_o[2*dp+1], al, b1h);
            }
        }
    }

    // ---- epilogue
    lr0 += __shfl_xor_sync(0xffffffffu, lr0, 1);
    lr0 += __shfl_xor_sync(0xffffffffu, lr0, 2);
    lr1 += __shfl_xor_sync(0xffffffffu, lr1, 1);
    lr1 += __shfl_xor_sync(0xffffffffu, lr1, 2);
    float il0 = 1.f / lr0, il1 = 1.f / lr1;
    const int row0 = q0 + wid * 16 + (lid >> 2);
    const int col0 = head * 64 + (lid & 3) * 2;
#pragma unroll
    for (int d = 0; d < 8; d++) {
        int col = col0 + d * 8;
        float o0 = acc_o[d][0] * il0, o1 = acc_o[d][1] * il0;
        float o2 = acc_o[d][2] * il1, o3 = acc_o[d][3] * il1;
        uint32_t h0 = pack_bf2(o0, o1), h1 = pack_bf2(o2, o3);
        *(uint32_t*)(Ohi + (size_t)row0 * 2048 + col) = h0;
        *(uint32_t*)(Ohi + (size_t)(row0 + 8) * 2048 + col) = h1;
        __nv_bfloat162 hh0 = *(__nv_bfloat162*)&h0;
        __nv_bfloat162 hh1 = *(__nv_bfloat162*)&h1;
        *(uint32_t*)(Olo + (size_t)row0 * 2048 + col) =
            pack_bf2(o0 - __bfloat162float(hh0.x), o1 - __bfloat162float(hh0.y));
        *(uint32_t*)(Olo + (size_t)(row0 + 8) * 2048 + col) =
            pack_bf2(o2 - __bfloat162float(hh1.x), o3 - __bfloat162float(hh1.y));
    }
}

// -------------------- conversion / elementwise kernels --------------------
__global__ void split_kernel(const float* __restrict__ x,
                             __nv_bfloat16* __restrict__ hi,
                             __nv_bfloat16* __restrict__ lo, int n4)
{
    int i = blockIdx.x * 256 + threadIdx.x;
    if (i < n4) {
        float4 v = ((const float4*)x)[i];
        __nv_bfloat16 h0 = __float2bfloat16(v.x), h1 = __float2bfloat16(v.y);
        __nv_bfloat16 h2 = __float2bfloat16(v.z), h3 = __float2bfloat16(v.w);
        __nv_bfloat162 ha; ha.x = h0; ha.y = h1;
        __nv_bfloat162 hb; hb.x = h2; hb.y = h3;
        ((__nv_bfloat162*)hi)[i * 2]     = ha;
        ((__nv_bfloat162*)hi)[i * 2 + 1] = hb;
        __nv_bfloat162 la, lb;
        la.x = __float2bfloat16(v.x - __bfloat162float(h0));
        la.y = __float2bfloat16(v.y - __bfloat162float(h1));
        lb.x = __float2bfloat16(v.z - __bfloat162float(h2));
        lb.y = __float2bfloat16(v.w - __bfloat162float(h3));
        ((__nv_bfloat162*)lo)[i * 2]     = la;
        ((__nv_bfloat162*)lo)[i * 2 + 1] = lb;
    }
}

__global__ void transpose_split(const float* __restrict__ x,
                                __nv_bfloat16* __restrict__ hiT,
                                __nv_bfloat16* __restrict__ loT, int R, int C)
{
    __shared__ float t[32][33];
    int c0 = blockIdx.x * 32, r0 = blockIdx.y * 32;
    for (int i = threadIdx.y; i < 32; i += 8)
        t[i][threadIdx.x] = x[(size_t)(r0 + i) * C + c0 + threadIdx.x];
    __syncthreads();
    for (int i = threadIdx.y; i < 32; i += 8) {
        float v = t[threadIdx.x][i];
        __nv_bfloat16 h = __float2bfloat16(v);
        size_t o = (size_t)(c0 + i) * R + r0 + threadIdx.x;
        hiT[o] = h;
        loT[o] = __float2bfloat16(v - __bfloat162float(h));
    }
}

__global__ void rmsnorm_kernel(const float* __restrict__ x,
                               const float* __restrict__ w,
                               float* __restrict__ y,
                               __nv_bfloat16* __restrict__ yhi,
                               __nv_bfloat16* __restrict__ ylo)
{
    const int row = blockIdx.x;
    const float* xr = x + (size_t)row * 2048;
    float ss = 0.f;
    for (int i = threadIdx.x; i < 2048; i += 256) { float v = xr[i]; ss += v * v; }
    __shared__ float red[256];
    red[threadIdx.x] = ss;
    __syncthreads();
    for (int s = 128; s > 0; s >>= 1) {
        if (threadIdx.x < s) red[threadIdx.x] += red[threadIdx.x + s];
        __syncthreads();
    }
    __shared__ float inv;
    if (threadIdx.x == 0) inv = rsqrtf(red[0] * (1.f / 2048.f) + 1e-6f);
    __syncthreads();
    float iv = inv;
    for (int i = threadIdx.x; i < 2048; i += 256) {
        float v = xr[i] * iv * w[i];
        size_t o = (size_t)row * 2048 + i;
        y[o] = v;
        __nv_bfloat16 h = __float2bfloat16(v);
        yhi[o] = h;
        ylo[o] = __float2bfloat16(v - __bfloat162float(h));
    }
}

__global__ void swiglu_split(const float* __restrict__ g, const float* __restrict__ u,
                             __nv_bfloat16* __restrict__ hi, __nv_bfloat16* __restrict__ lo,
                             int n)
{
    int i = blockIdx.x * blockDim.x + threadIdx.x;
    if (i < n) {
        float x = g[i];
        float v = (x / (1.f + __expf(-x))) * u[i];
        __nv_bfloat16 h = __float2bfloat16(v);
        hi[i] = h;
        lo[i] = __float2bfloat16(v - __bfloat162float(h));
    }
}

// -------------------- orchestration --------------------
static const int SMEM_GEMM = 3 * 32768;   // 96KB
static const int SMEM_ATTN = 16384 + 3 * 16384;  // 64KB

extern "C" void kernel_launch(void* const* d_in, const int* in_sizes, int n_in,
                              void* d_out, int out_size)
{
    (void)in_sizes; (void)n_in; (void)out_size;
    const float* hidden      = (const float*)d_in[0];
    const float* comp_w      = (const float*)d_in[1];
    const float* comp_b      = (const float*)d_in[2];
    const float* q_w         = (const float*)d_in[3];
    const float* k_w         = (const float*)d_in[4];
    const float* v_w         = (const float*)d_in[5];
    const float* o_w         = (const float*)d_in[6];
    const float* attn_norm_w = (const float*)d_in[7];
    const float* mlp_norm_w  = (const float*)d_in[8];
    const float* gate_w      = (const float*)d_in[9];
    const float* up_w        = (const float*)d_in[10];
    const float* down_w      = (const float*)d_in[11];
    float* out = (float*)d_out;

    cudaFuncSetAttribute(bgemm<0,0>, cudaFuncAttributeMaxDynamicSharedMemorySize, SMEM_GEMM);
    cudaFuncSetAttribute(bgemm<0,1>, cudaFuncAttributeMaxDynamicSharedMemorySize, SMEM_GEMM);
    cudaFuncSetAttribute(bgemm<1,0>, cudaFuncAttributeMaxDynamicSharedMemorySize, SMEM_GEMM);
    cudaFuncSetAttribute(bgemm<2,0>, cudaFuncAttributeMaxDynamicSharedMemorySize, SMEM_GEMM);
    cudaFuncSetAttribute(attn_mma, cudaFuncAttributeMaxDynamicSharedMemorySize, SMEM_ATTN);

    float *compressed, *ct, *gate, *up;
    cudaGetSymbolAddress((void**)&compressed, g_compressed);
    cudaGetSymbolAddress((void**)&ct,         g_ct);
    cudaGetSymbolAddress((void**)&gate,       g_gate);
    cudaGetSymbolAddress((void**)&up,         g_up);

    __nv_bfloat16 *res_hi, *res_lo, *ct_hi, *ct_lo, *ao_hi, *ao_lo, *ga_hi, *ga_lo,
                  *hT_hi, *hT_lo, *q_hi, *q_lo, *k_hi, *k_lo, *v_hi, *v_lo,
                  *cw_hi, *cw_lo, *qw_hi, *qw_lo, *kw_hi, *kw_lo,
                  *vw_hi, *vw_lo, *ow_hi, *ow_lo, *gw_hi, *gw_lo, *uw_hi, *uw_lo,
                  *dw_hi, *dw_lo;
    cudaGetSymbolAddress((void**)&res_hi, g_res_hi); cudaGetSymbolAddress((void**)&res_lo, g_res_lo);
    cudaGetSymbolAddress((void**)&ct_hi,  g_ct_hi);  cudaGetSymbolAddress((void**)&ct_lo,  g_ct_lo);
    cudaGetSymbolAddress((void**)&ao_hi,  g_ao_hi);  cudaGetSymbolAddress((void**)&ao_lo,  g_ao_lo);
    cudaGetSymbolAddress((void**)&ga_hi,  g_ga_hi);  cudaGetSymbolAddress((void**)&ga_lo,  g_ga_lo);
    cudaGetSymbolAddress((void**)&hT_hi,  g_hT_hi);  cudaGetSymbolAddress((void**)&hT_lo,  g_hT_lo);
    cudaGetSymbolAddress((void**)&q_hi,   g_q_hi);   cudaGetSymbolAddress((void**)&q_lo,   g_q_lo);
    cudaGetSymbolAddress((void**)&k_hi,   g_k_hi);   cudaGetSymbolAddress((void**)&k_lo,   g_k_lo);
    cudaGetSymbolAddress((void**)&v_hi,   g_v_hi);   cudaGetSymbolAddress((void**)&v_lo,   g_v_lo);
    cudaGetSymbolAddress((void**)&cw_hi,  g_cw_hi);  cudaGetSymbolAddress((void**)&cw_lo,  g_cw_lo);
    cudaGetSymbolAddress((void**)&qw_hi,  g_qw_hi);  cudaGetSymbolAddress((void**)&qw_lo,  g_qw_lo);
    cudaGetSymbolAddress((void**)&kw_hi,  g_kw_hi);  cudaGetSymbolAddress((void**)&kw_lo,  g_kw_lo);
    cudaGetSymbolAddress((void**)&vw_hi,  g_vw_hi);  cudaGetSymbolAddress((void**)&vw_lo,  g_vw_lo);
    cudaGetSymbolAddress((void**)&ow_hi,  g_ow_hi);  cudaGetSymbolAddress((void**)&ow_lo,  g_ow_lo);
    cudaGetSymbolAddress((void**)&gw_hi,  g_gw_hi);  cudaGetSymbolAddress((void**)&gw_lo,  g_gw_lo);
    cudaGetSymbolAddress((void**)&uw_hi,  g_uw_hi);  cudaGetSymbolAddress((void**)&uw_lo,  g_uw_lo);
    cudaGetSymbolAddress((void**)&dw_hi,  g_dw_hi);  cudaGetSymbolAddress((void**)&dw_lo,  g_dw_lo);

    auto split = [&](const float* src, __nv_bfloat16* hi, __nv_bfloat16* lo, int n) {
        int n4 = n / 4;
        split_kernel<<<(n4 + 255) / 256, 256>>>(src, hi, lo, n4);
    };

    split(comp_w, cw_hi, cw_lo, 1024 * 2048);
    split(q_w,    qw_hi, qw_lo, 2048 * 2048);
    split(k_w,    kw_hi, kw_lo, 512 * 2048);
    split(v_w,    vw_hi, vw_lo, 512 * 2048);
    split(o_w,    ow_hi, ow_lo, 2048 * 2048);
    split(gate_w, gw_hi, gw_lo, 5632 * 2048);
    split(up_w,   uw_hi, uw_lo, 5632 * 2048);
    split(down_w, dw_hi, dw_lo, 2048 * 5632);
    transpose_split<<<dim3(64, 64), dim3(32, 8)>>>(hidden, hT_hi, hT_lo, 2048, 2048);
    split(hidden, res_hi, res_lo, 2048 * 2048);

    // compressed = comp_w @ hidden + comp_b
    bgemm<1,0><<<dim3(16, 8), 256, SMEM_GEMM>>>(cw_hi, cw_lo, hT_hi, hT_lo,
        compressed, comp_b, nullptr, nullptr, 1024, 2048, 2048);

    for (int layer = 0; layer < 2; layer++) {
        split(compressed, res_hi + 2048 * 2048, res_lo + 2048 * 2048, 1024 * 2048);
        rmsnorm_kernel<<<1024, 256>>>(compressed, attn_norm_w, ct, ct_hi, ct_lo);

        bgemm<0,1><<<dim3(16, 8), 256, SMEM_GEMM>>>(ct_hi, ct_lo, qw_hi, qw_lo,
            nullptr, nullptr, q_hi, q_lo, 1024, 2048, 2048);
        bgemm<0,1><<<dim3(4, 24), 256, SMEM_GEMM>>>(res_hi, res_lo, kw_hi, kw_lo,
            nullptr, nullptr, k_hi, k_lo, 3072, 512, 2048);
        bgemm<0,1><<<dim3(4, 24), 256, SMEM_GEMM>>>(res_hi, res_lo, vw_hi, vw_lo,
            nullptr, nullptr, v_hi, v_lo, 3072, 512, 2048);

        attn_mma<<<dim3(16, 32), 128, SMEM_ATTN>>>(q_hi, q_lo, k_hi, k_lo,
                                                   v_hi, v_lo, ao_hi, ao_lo);

        bgemm<2,0><<<dim3(16, 8), 256, SMEM_GEMM>>>(ao_hi, ao_lo, ow_hi, ow_lo,
            compressed, ct, nullptr, nullptr, 1024, 2048, 2048);

        rmsnorm_kernel<<<1024, 256>>>(compressed, mlp_norm_w, ct, ct_hi, ct_lo);

        bgemm<0,0><<<dim3(44, 8), 256, SMEM_GEMM>>>(ct_hi, ct_lo, gw_hi, gw_lo,
            gate, nullptr, nullptr, nullptr, 1024, 5632, 2048);
        bgemm<0,0><<<dim3(44, 8), 256, SMEM_GEMM>>>(ct_hi, ct_lo, uw_hi, uw_lo,
            up, nullptr, nullptr, nullptr, 1024, 5632, 2048);

        swiglu_split<<<(1024 * 5632 + 255) / 256, 256>>>(gate, up, ga_hi, ga_lo, 1024 * 5632);

        float* dst = (layer == 1) ? out : compressed;
        bgemm<2,0><<<dim3(16, 8), 256, SMEM_GEMM>>>(ga_hi, ga_lo, dw_hi, dw_lo,
            dst, ct, nullptr, nullptr, 1024, 2048, 5632);
    }
}

// round 7
// speedup vs baseline: 3.2924x; 1.0151x over previous
#include <cuda_runtime.h>
#include <cuda_bf16.h>
#include <cstdint>
#include <math.h>

// ===========================================================================
// S=2048, H=2048, COMP=1024, T=3072, KV_DIM=512, FF=5632, NH=32, NKV=8,
// HD=64, DEPTH=2. mma.sync.m16n8k16 bf16 hi/lo 3-product split everywhere.
// R6: epilogue fusions (swiglu, residual-split), K/V merged launch, ILP splits.
// ===========================================================================

// -------------------- device-global scratch (no allocs) --------------------
__device__ float g_compressed[1024 * 2048];
__device__ float g_ct[1024 * 2048];
__device__ float g_gate[1024 * 5632];

__device__ __nv_bfloat16 g_res_hi[3072 * 2048], g_res_lo[3072 * 2048];
__device__ __nv_bfloat16 g_ct_hi[1024 * 2048], g_ct_lo[1024 * 2048];
__device__ __nv_bfloat16 g_ao_hi[1024 * 2048], g_ao_lo[1024 * 2048];
__device__ __nv_bfloat16 g_ga_hi[1024 * 5632], g_ga_lo[1024 * 5632];
__device__ __nv_bfloat16 g_hT_hi[2048 * 2048], g_hT_lo[2048 * 2048];

__device__ __nv_bfloat16 g_q_hi[1024 * 2048], g_q_lo[1024 * 2048];
__device__ __nv_bfloat16 g_k_hi[3072 * 512],  g_k_lo[3072 * 512];
__device__ __nv_bfloat16 g_v_hi[3072 * 512],  g_v_lo[3072 * 512];

__device__ __nv_bfloat16 g_cw_hi[1024 * 2048], g_cw_lo[1024 * 2048];
__device__ __nv_bfloat16 g_qw_hi[2048 * 2048], g_qw_lo[2048 * 2048];
__device__ __nv_bfloat16 g_kw_hi[512 * 2048],  g_kw_lo[512 * 2048];
__device__ __nv_bfloat16 g_vw_hi[512 * 2048],  g_vw_lo[512 * 2048];
__device__ __nv_bfloat16 g_ow_hi[2048 * 2048], g_ow_lo[2048 * 2048];
__device__ __nv_bfloat16 g_gw_hi[5632 * 2048], g_gw_lo[5632 * 2048];
__device__ __nv_bfloat16 g_uw_hi[5632 * 2048], g_uw_lo[5632 * 2048];
__device__ __nv_bfloat16 g_dw_hi[2048 * 5632], g_dw_lo[2048 * 5632];

// -------------------- helpers --------------------
__device__ __forceinline__ uint32_t smem_u32(const void* p) {
    return (uint32_t)__cvta_generic_to_shared(p);
}

#define LDSM_X4(r0, r1, r2, r3, addr)                                          \
    asm volatile("ldmatrix.sync.aligned.m8n8.x4.shared.b16 {%0,%1,%2,%3}, [%4];" \
                 : "=r"(r0), "=r"(r1), "=r"(r2), "=r"(r3) : "r"(addr))
#define LDSM_X4_T(r0, r1, r2, r3, addr)                                        \
    asm volatile("ldmatrix.sync.aligned.m8n8.x4.trans.shared.b16 {%0,%1,%2,%3}, [%4];" \
                 : "=r"(r0), "=r"(r1), "=r"(r2), "=r"(r3) : "r"(addr))

#define MMA_BF16(ac, ar, br)                                                   \
    asm volatile(                                                              \
        "mma.sync.aligned.m16n8k16.row.col.f32.bf16.bf16.f32 "                 \
        "{%0,%1,%2,%3},{%4,%5,%6,%7},{%8,%9},{%0,%1,%2,%3};"                   \
        : "+f"((ac)[0]), "+f"((ac)[1]), "+f"((ac)[2]), "+f"((ac)[3])           \
        : "r"((ar)[0]), "r"((ar)[1]), "r"((ar)[2]), "r"((ar)[3]),              \
          "r"((br)[0]), "r"((br)[1]))

#define CP_ASYNC16(dst, src)                                                   \
    asm volatile("cp.async.cg.shared.global [%0], [%1], 16;" :: "r"(dst), "l"(src))
#define CP_COMMIT() asm volatile("cp.async.commit_group;")
#define CP_WAIT1()  asm volatile("cp.async.wait_group 1;")

__device__ __forceinline__ uint32_t pack_bf2(float x, float y) {
    __nv_bfloat162 h = __floats2bfloat162_rn(x, y);
    return *(uint32_t*)&h;
}

// ==================== HMMA split-bf16 GEMM body ====================
// C = (Ahi+Alo)[M,K] @ (Bhi+Blo)[N,K]^T. BM=BN=128, BK=32, 3-stage cp.async.
// EPI: 0 none, 1 +aux[row], 2 +aux[row*N+col], 3 silu(aux[row*N+col])*acc
// OUT: 0 fp32 C; 1 bf16 hi/lo; 2 both
__device__ __forceinline__ void load_stage(
    uint32_t sb, int kc, int tid, int m0, int n0, int K,
    const __nv_bfloat16* __restrict__ Ahi, const __nv_bfloat16* __restrict__ Alo,
    const __nv_bfloat16* __restrict__ Bhi, const __nv_bfloat16* __restrict__ Blo)
{
    const int kb = kc * 32;
#pragma unroll
    for (int i = 0; i < 2; i++) {
        int f = tid + i * 256;
        int r = f >> 2, c = f & 3;
        uint32_t off = (uint32_t)(r * 64) + (uint32_t)((c * 16) ^ ((r & 3) << 4));
        size_t ga = (size_t)(m0 + r) * K + kb + c * 8;
        size_t gb = (size_t)(n0 + r) * K + kb + c * 8;
        CP_ASYNC16(sb + off,         Ahi + ga);
        CP_ASYNC16(sb + 8192 + off,  Alo + ga);
        CP_ASYNC16(sb + 16384 + off, Bhi + gb);
        CP_ASYNC16(sb + 24576 + off, Blo + gb);
    }
}

template <int EPI, int OUT>
__device__ __forceinline__ void bgemm_body(
    const __nv_bfloat16* __restrict__ Ahi, const __nv_bfloat16* __restrict__ Alo,
    const __nv_bfloat16* __restrict__ Bhi, const __nv_bfloat16* __restrict__ Blo,
    float* __restrict__ C, const float* __restrict__ aux,
    __nv_bfloat16* __restrict__ Chi, __nv_bfloat16* __restrict__ Clo,
    int M, int N, int K)
{
    extern __shared__ char dsm[];
    const int tid = threadIdx.x;
    const int wid = tid >> 5, lid = tid & 31;
    const int wm = wid & 3, wn = wid >> 2;
    const int m0 = blockIdx.y * 128;
    const int n0 = blockIdx.x * 128;
    const uint32_t sbase = smem_u32(dsm);

    const int arow = wm * 32 + (lid & 7) + ((lid >> 3) & 1) * 8;
    const uint32_t a_base = (uint32_t)(arow * 64);
    const uint32_t a_sw = (uint32_t)((arow & 3) << 4);
    const uint32_t a_k = (uint32_t)((lid >> 4) & 1) * 16;

    const int brow = wn * 64 + (lid & 7) + ((lid >> 4) & 1) * 8;
    const uint32_t b_base = (uint32_t)(brow * 64);
    const uint32_t b_sw = (uint32_t)((brow & 3) << 4);
    const uint32_t b_k = (uint32_t)((lid >> 3) & 1) * 16;

    float acc[2][8][4];
#pragma unroll
    for (int mt = 0; mt < 2; mt++)
#pragma unroll
        for (int nt = 0; nt < 8; nt++)
#pragma unroll
            for (int e = 0; e < 4; e++) acc[mt][nt][e] = 0.f;

    const int NK = K / 32;
    load_stage(sbase, 0, tid, m0, n0, K, Ahi, Alo, Bhi, Blo);
    CP_COMMIT();
    load_stage(sbase + 32768, 1, tid, m0, n0, K, Ahi, Alo, Bhi, Blo);
    CP_COMMIT();

    for (int kc = 0; kc < NK; kc++) {
        CP_WAIT1();
        __syncthreads();
        if (kc + 2 < NK)
            load_stage(sbase + (uint32_t)((kc + 2) % 3) * 32768, kc + 2, tid,
                       m0, n0, K, Ahi, Alo, Bhi, Blo);
        CP_COMMIT();

        const uint32_t st = sbase + (uint32_t)(kc % 3) * 32768;
#pragma unroll
        for (int ks = 0; ks < 2; ks++) {
            const uint32_t ako = (a_k + (uint32_t)ks * 32) ^ a_sw;
            const uint32_t bko = (b_k + (uint32_t)ks * 32) ^ b_sw;
            uint32_t ah[2][4], al[2][4], bb[8][2];
#pragma unroll
            for (int mt = 0; mt < 2; mt++) {
                LDSM_X4(ah[mt][0], ah[mt][1], ah[mt][2], ah[mt][3],
                        st + a_base + (uint32_t)mt * 1024 + ako);
                LDSM_X4(al[mt][0], al[mt][1], al[mt][2], al[mt][3],
                        st + 8192 + a_base + (uint32_t)mt * 1024 + ako);
            }
#pragma unroll
            for (int p = 0; p < 4; p++) {
                LDSM_X4(bb[2*p][0], bb[2*p][1], bb[2*p+1][0], bb[2*p+1][1],
                        st + 16384 + b_base + (uint32_t)p * 1024 + bko);
            }
#pragma unroll
            for (int nt = 0; nt < 8; nt++)
#pragma unroll
                for (int mt = 0; mt < 2; mt++)
                    MMA_BF16(acc[mt][nt], ah[mt], bb[nt]);
#pragma unroll
            for (int nt = 0; nt < 8; nt++)
#pragma unroll
                for (int mt = 0; mt < 2; mt++)
                    MMA_BF16(acc[mt][nt], al[mt], bb[nt]);
#pragma unroll
            for (int p = 0; p < 4; p++) {
                LDSM_X4(bb[2*p][0], bb[2*p][1], bb[2*p+1][0], bb[2*p+1][1],
                        st + 24576 + b_base + (uint32_t)p * 1024 + bko);
            }
#pragma unroll
            for (int nt = 0; nt < 8; nt++)
#pragma unroll
                for (int mt = 0; mt < 2; mt++)
                    MMA_BF16(acc[mt][nt], ah[mt], bb[nt]);
        }
    }

    const int grow0 = m0 + wm * 32 + (lid >> 2);
    const int gcol0 = n0 + wn * 64 + (lid & 3) * 2;
#pragma unroll
    for (int mt = 0; mt < 2; mt++) {
#pragma unroll
        for (int nt = 0; nt < 8; nt++) {
            int r0 = grow0 + mt * 16;
            int c0 = gcol0 + nt * 8;
            float2 v0 = make_float2(acc[mt][nt][0], acc[mt][nt][1]);
            float2 v1 = make_float2(acc[mt][nt][2], acc[mt][nt][3]);
            if (EPI == 1) {
                float b0 = aux[r0], b1 = aux[r0 + 8];
                v0.x += b0; v0.y += b0; v1.x += b1; v1.y += b1;
            }
            if (EPI == 2) {
                const float2 a0 = *(const float2*)(aux + (size_t)r0 * N + c0);
                const float2 a1 = *(const float2*)(aux + (size_t)(r0 + 8) * N + c0);
                v0.x += a0.x; v0.y += a0.y; v1.x += a1.x; v1.y += a1.y;
            }
            if (EPI == 3) {
                const float2 a0 = *(const float2*)(aux + (size_t)r0 * N + c0);
                const float2 a1 = *(const float2*)(aux + (size_t)(r0 + 8) * N + c0);
                v0.x *= a0.x / (1.f + __expf(-a0.x));
                v0.y *= a0.y / (1.f + __expf(-a0.y));
                v1.x *= a1.x / (1.f + __expf(-a1.x));
                v1.y *= a1.y / (1.f + __expf(-a1.y));
            }
            if (OUT == 0 || OUT == 2) {
                *(float2*)(C + (size_t)r0 * N + c0) = v0;
                *(float2*)(C + (size_t)(r0 + 8) * N + c0) = v1;
            }
            if (OUT == 1 || OUT == 2) {
                uint32_t h0 = pack_bf2(v0.x, v0.y);
                uint32_t h1 = pack_bf2(v1.x, v1.y);
                *(uint32_t*)(Chi + (size_t)r0 * N + c0) = h0;
                *(uint32_t*)(Chi + (size_t)(r0 + 8) * N + c0) = h1;
                __nv_bfloat162 hh0 = *(__nv_bfloat162*)&h0;
                __nv_bfloat162 hh1 = *(__nv_bfloat162*)&h1;
                *(uint32_t*)(Clo + (size_t)r0 * N + c0) =
                    pack_bf2(v0.x - __bfloat162float(hh0.x),
                             v0.y - __bfloat162float(hh0.y));
                *(uint32_t*)(Clo + (size_t)(r0 + 8) * N + c0) =
                    pack_bf2(v1.x - __bfloat162float(hh1.x),
                             v1.y - __bfloat162float(hh1.y));
            }
        }
    }
}

template <int EPI, int OUT>
__global__ __launch_bounds__(256, 2) void bgemm(
    const __nv_bfloat16* __restrict__ Ahi, const __nv_bfloat16* __restrict__ Alo,
    const __nv_bfloat16* __restrict__ Bhi, const __nv_bfloat16* __restrict__ Blo,
    float* __restrict__ C, const float* __restrict__ aux,
    __nv_bfloat16* __restrict__ Chi, __nv_bfloat16* __restrict__ Clo,
    int M, int N, int K)
{
    bgemm_body<EPI, OUT>(Ahi, Alo, Bhi, Blo, C, aux, Chi, Clo, M, N, K);
}

// K and V projections in one launch (blockIdx.z selects weight/output)
__global__ __launch_bounds__(256, 2) void bgemm_kv(
    const __nv_bfloat16* __restrict__ Ahi, const __nv_bfloat16* __restrict__ Alo,
    const __nv_bfloat16* __restrict__ B1hi, const __nv_bfloat16* __restrict__ B1lo,
    __nv_bfloat16* __restrict__ C1hi, __nv_bfloat16* __restrict__ C1lo,
    const __nv_bfloat16* __restrict__ B2hi, const __nv_bfloat16* __restrict__ B2lo,
    __nv_bfloat16* __restrict__ C2hi, __nv_bfloat16* __restrict__ C2lo,
    int M, int N, int K)
{
    if (blockIdx.z == 0)
        bgemm_body<0, 1>(Ahi, Alo, B1hi, B1lo, nullptr, nullptr, C1hi, C1lo, M, N, K);
    else
        bgemm_body<0, 1>(Ahi, Alo, B2hi, B2lo, nullptr, nullptr, C2hi, C2lo, M, N, K);
}

// ==================== HMMA split-bf16 flash attention ====================
__global__ __launch_bounds__(128, 3) void attn_mma(
    const __nv_bfloat16* __restrict__ Qhi, const __nv_bfloat16* __restrict__ Qlo,
    const __nv_bfloat16* __restrict__ Khi, const __nv_bfloat16* __restrict__ Klo,
    const __nv_bfloat16* __restrict__ Vhi, const __nv_bfloat16* __restrict__ Vlo,
    __nv_bfloat16* __restrict__ Ohi, __nv_bfloat16* __restrict__ Olo)
{
    extern __shared__ char sm[];
    const int tid = threadIdx.x;
    const int wid = tid >> 5, lid = tid & 31;
    const int q0 = blockIdx.x * 64;
    const int head = blockIdx.y;
    const int kvoff = (head >> 2) * 64;
    const uint32_t sb = smem_u32(sm);
    const uint32_t sQh = sb, sQl = sb + 8192;
    const uint32_t sKV = sb + 16384;

#pragma unroll
    for (int i = 0; i < 4; i++) {
        int f = tid + i * 128;
        int r = f >> 3, c = f & 7;
        uint32_t off = (uint32_t)(r * 128) + (uint32_t)((c * 16) ^ ((r & 7) << 4));
        size_t g = (size_t)(q0 + r) * 2048 + head * 64 + c * 8;
        CP_ASYNC16(sQh + off, Qhi + g);
        CP_ASYNC16(sQl + off, Qlo + g);
    }
    CP_COMMIT();

#define ISSUE_KV(t0, st)                                                       \
    {                                                                          \
        uint32_t s_ = sKV + (uint32_t)(st) * 16384;                            \
        _Pragma("unroll")                                                      \
        for (int i_ = 0; i_ < 2; i_++) {                                       \
            int f_ = tid + i_ * 128;                                           \
            int r_ = f_ >> 3, c_ = f_ & 7;                                     \
            uint32_t o_ = (uint32_t)(r_ * 128) +                               \
                          (uint32_t)((c_ * 16) ^ ((r_ & 7) << 4));             \
            size_t g_ = (size_t)((t0) + r_) * 512 + kvoff + c_ * 8;            \
            CP_ASYNC16(s_ + o_,         Khi + g_);                             \
            CP_ASYNC16(s_ + 4096 + o_,  Klo + g_);                             \
            CP_ASYNC16(s_ + 8192 + o_,  Vhi + g_);                             \
            CP_ASYNC16(s_ + 12288 + o_, Vlo + g_);                             \
        }                                                                      \
    }

    ISSUE_KV(0, 0);  CP_COMMIT();
    ISSUE_KV(32, 1); CP_COMMIT();

    asm volatile("cp.async.wait_group 2;");
    __syncthreads();

    uint32_t qh[4][4], ql[4][4];
    {
        const int ar = (lid & 7) + ((lid >> 3) & 1) * 8;
        const int row = wid * 16 + ar;
        const uint32_t khalf = (uint32_t)((lid >> 4) & 1) * 16;
#pragma unroll
        for (int ks = 0; ks < 4; ks++) {
            uint32_t off = (uint32_t)(row * 128) +
                           ((khalf + (uint32_t)ks * 32) ^ ((uint32_t)(ar & 7) << 4));
            LDSM_X4(qh[ks][0], qh[ks][1], qh[ks][2], qh[ks][3], sQh + off);
            LDSM_X4(ql[ks][0], ql[ks][1], ql[ks][2], ql[ks][3], sQl + off);
        }
    }

    float acc_o[8][4];
#pragma unroll
    for (int d = 0; d < 8; d++)
#pragma unroll
        for (int e = 0; e < 4; e++) acc_o[d][e] = 0.f;
    float mr0 = -1e30f, mr1 = -1e30f, lr0 = 0.f, lr1 = 0.f;

    const int brS = (lid & 7) + ((lid >> 4) & 1) * 8;
    const uint32_t bkS = (uint32_t)((lid >> 3) & 1) * 16;
    const int trV = (lid & 7) + ((lid >> 3) & 1) * 8;
    const uint32_t dkV = (uint32_t)((lid >> 4) & 1) * 16;

    for (int t = 0; t < 96; t++) {
        if (t + 1 < 96) { CP_WAIT1(); } else { asm volatile("cp.async.wait_group 0;"); }
        __syncthreads();
        if (t + 2 < 96) ISSUE_KV((t + 2) * 32, (t + 2) % 3);
        CP_COMMIT();
        const uint32_t st = sKV + (uint32_t)(t % 3) * 16384;

        float s[4][4];
#pragma unroll
        for (int nt = 0; nt < 4; nt++)
#pragma unroll
            for (int e = 0; e < 4; e++) s[nt][e] = 0.f;
#pragma unroll
        for (int ks = 0; ks < 4; ks++) {
            uint32_t bh[4][2], bl[4][2];
#pragma unroll
            for (int p = 0; p < 2; p++) {
                int rr = p * 16 + brS;
                uint32_t off = (uint32_t)(rr * 128) +
                               ((bkS + (uint32_t)ks * 32) ^ ((uint32_t)(rr & 7) << 4));
                LDSM_X4(bh[2*p][0], bh[2*p][1], bh[2*p+1][0], bh[2*p+1][1], st + off);
                LDSM_X4(bl[2*p][0], bl[2*p][1], bl[2*p+1][0], bl[2*p+1][1], st + 4096 + off);
            }
#pragma unroll
            for (int nt = 0; nt < 4; nt++) {
                MMA_BF16(s[nt], qh[ks], bh[nt]);
                MMA_BF16(s[nt], qh[ks], bl[nt]);
                MMA_BF16(s[nt], ql[ks], bh[nt]);
            }
        }

        float mn0 = mr0, mn1 = mr1;
#pragma unroll
        for (int nt = 0; nt < 4; nt++) {
            s[nt][0] *= 0.125f; s[nt][1] *= 0.125f;
            s[nt][2] *= 0.125f; s[nt][3] *= 0.125f;
            mn0 = fmaxf(mn0, fmaxf(s[nt][0], s[nt][1]));
            mn1 = fmaxf(mn1, fmaxf(s[nt][2], s[nt][3]));
        }
        mn0 = fmaxf(mn0, __shfl_xor_sync(0xffffffffu, mn0, 1));
        mn0 = fmaxf(mn0, __shfl_xor_sync(0xffffffffu, mn0, 2));
        mn1 = fmaxf(mn1, __shfl_xor_sync(0xffffffffu, mn1, 1));
        mn1 = fmaxf(mn1, __shfl_xor_sync(0xffffffffu, mn1, 2));
        float f0 = __expf(mr0 - mn0), f1 = __expf(mr1 - mn1);
        mr0 = mn0; mr1 = mn1;
        float ps0 = 0.f, ps1 = 0.f;
#pragma unroll
        for (int nt = 0; nt < 4; nt++) {
            s[nt][0] = __expf(s[nt][0] - mn0);
            s[nt][1] = __expf(s[nt][1] - mn0);
            s[nt][2] = __expf(s[nt][2] - mn1);
            s[nt][3] = __expf(s[nt][3] - mn1);
            ps0 += s[nt][0] + s[nt][1];
            ps1 += s[nt][2] + s[nt][3];
        }
        lr0 = lr0 * f0 + ps0;
        lr1 = lr1 * f1 + ps1;
#pragma unroll
        for (int d = 0; d < 8; d++) {
            acc_o[d][0] *= f0; acc_o[d][1] *= f0;
            acc_o[d][2] *= f1; acc_o[d][3] *= f1;
        }

#pragma unroll
        for (int j = 0; j < 2; j++) {
            uint32_t ah[4], al[4];
            {
                float p00 = s[2*j][0],   p01 = s[2*j][1];
                float p02 = s[2*j][2],   p03 = s[2*j][3];
                float p10 = s[2*j+1][0], p11 = s[2*j+1][1];
                float p12 = s[2*j+1][2], p13 = s[2*j+1][3];
                ah[0] = pack_bf2(p00, p01); ah[1] = pack_bf2(p02, p03);
                ah[2] = pack_bf2(p10, p11); ah[3] = pack_bf2(p12, p13);
#pragma unroll
                for (int e = 0; e < 4; e++) {
                    __nv_bfloat162 hh = *(__nv_bfloat162*)&ah[e];
                    float x0, x1;
                    if (e == 0) { x0 = p00; x1 = p01; }
                    else if (e == 1) { x0 = p02; x1 = p03; }
                    else if (e == 2) { x0 = p10; x1 = p11; }
                    else { x0 = p12; x1 = p13; }
                    al[e] = pack_bf2(x0 - __bfloat162float(hh.x),
                                     x1 - __bfloat162float(hh.y));
                }
            }
            const int rr = j * 16 + trV;
#pragma unroll
            for (int dp = 0; dp < 4; dp++) {
                uint32_t off = (uint32_t)(rr * 128) +
                               ((dkV + (uint32_t)dp * 32) ^ ((uint32_t)(rr & 7) << 4));
                uint32_t vh[4], vl[4];
                LDSM_X4_T(vh[0], vh[1], vh[2], vh[3], st + 8192 + off);
                LDSM_X4_T(vl[0], vl[1], vl[2], vl[3], st + 12288 + off);
                uint32_t b0h[2] = {vh[0], vh[1]}, b1h[2] = {vh[2], vh[3]};
                uint32_t b0l[2] = {vl[0], vl[1]}, b1l[2] = {vl[2], vl[3]};
                MMA_BF16(acc_o[2*dp],   ah, b0h);
                MMA_BF16(acc_o[2*dp],   ah, b0l);
                MMA_BF16(acc_o[2*dp],   al, b0h);
                MMA_BF16(acc_o[2*dp+1], ah, b1h);
                MMA_BF16(acc_o[2*dp+1], ah, b1l);
                MMA_BF16(acc_o[2*dp+1], al, b1h);
            }
        }
    }

    lr0 += __shfl_xor_sync(0xffffffffu, lr0, 1);
    lr0 += __shfl_xor_sync(0xffffffffu, lr0, 2);
    lr1 += __shfl_xor_sync(0xffffffffu, lr1, 1);
    lr1 += __shfl_xor_sync(0xffffffffu, lr1, 2);
    float il0 = 1.f / lr0, il1 = 1.f / lr1;
    const int row0 = q0 + wid * 16 + (lid >> 2);
    const int col0 = head * 64 + (lid & 3) * 2;
#pragma unroll
    for (int d = 0; d < 8; d++) {
        int col = col0 + d * 8;
        float o0 = acc_o[d][0] * il0, o1 = acc_o[d][1] * il0;
        float o2 = acc_o[d][2] * il1, o3 = acc_o[d][3] * il1;
        uint32_t h0 = pack_bf2(o0, o1), h1 = pack_bf2(o2, o3);
        *(uint32_t*)(Ohi + (size_t)row0 * 2048 + col) = h0;
        *(uint32_t*)(Ohi + (size_t)(row0 + 8) * 2048 + col) = h1;
        __nv_bfloat162 hh0 = *(__nv_bfloat162*)&h0;
        __nv_bfloat162 hh1 = *(__nv_bfloat162*)&h1;
        *(uint32_t*)(Olo + (size_t)row0 * 2048 + col) =
            pack_bf2(o0 - __bfloat162float(hh0.x), o1 - __bfloat162float(hh0.y));
        *(uint32_t*)(Olo + (size_t)(row0 + 8) * 2048 + col) =
            pack_bf2(o2 - __bfloat162float(hh1.x), o3 - __bfloat162float(hh1.y));
    }
}

// -------------------- conversion / elementwise kernels --------------------
// 4 float4s per thread (predicated) for MLP=4
__global__ void split_kernel(const float* __restrict__ x,
                             __nv_bfloat16* __restrict__ hi,
                             __nv_bfloat16* __restrict__ lo, int n4)
{
    int i = blockIdx.x * 1024 + threadIdx.x;
#pragma unroll
    for (int u = 0; u < 4; u++, i += 256) {
        if (i < n4) {
            float4 v = ((const float4*)x)[i];
            __nv_bfloat16 h0 = __float2bfloat16(v.x), h1 = __float2bfloat16(v.y);
            __nv_bfloat16 h2 = __float2bfloat16(v.z), h3 = __float2bfloat16(v.w);
            __nv_bfloat162 ha; ha.x = h0; ha.y = h1;
            __nv_bfloat162 hb; hb.x = h2; hb.y = h3;
            ((__nv_bfloat162*)hi)[i * 2]     = ha;
            ((__nv_bfloat162*)hi)[i * 2 + 1] = hb;
            __nv_bfloat162 la, lb;
            la.x = __float2bfloat16(v.x - __bfloat162float(h0));
            la.y = __float2bfloat16(v.y - __bfloat162float(h1));
            lb.x = __float2bfloat16(v.z - __bfloat162float(h2));
            lb.y = __float2bfloat16(v.w - __bfloat162float(h3));
            ((__nv_bfloat162*)lo)[i * 2]     = la;
            ((__nv_bfloat162*)lo)[i * 2 + 1] = lb;
        }
    }
}

__global__ void transpose_split(const float* __restrict__ x,
                                __nv_bfloat16* __restrict__ hiT,
                                __nv_bfloat16* __restrict__ loT, int R, int C)
{
    __shared__ float t[32][33];
    int c0 = blockIdx.x * 32, r0 = blockIdx.y * 32;
    for (int i = threadIdx.y; i < 32; i += 8)
        t[i][threadIdx.x] = x[(size_t)(r0 + i) * C + c0 + threadIdx.x];
    __syncthreads();
    for (int i = threadIdx.y; i < 32; i += 8) {
        float v = t[threadIdx.x][i];
        __nv_bfloat16 h = __float2bfloat16(v);
        size_t o = (size_t)(c0 + i) * R + r0 + threadIdx.x;
        hiT[o] = h;
        loT[o] = __float2bfloat16(v - __bfloat162float(h));
    }
}

__global__ void rmsnorm_kernel(const float* __restrict__ x,
                               const float* __restrict__ w,
                               float* __restrict__ y,
                               __nv_bfloat16* __restrict__ yhi,
                               __nv_bfloat16* __restrict__ ylo)
{
    const int row = blockIdx.x;
    const float* xr = x + (size_t)row * 2048;
    float ss = 0.f;
    for (int i = threadIdx.x; i < 2048; i += 256) { float v = xr[i]; ss += v * v; }
    __shared__ float red[256];
    red[threadIdx.x] = ss;
    __syncthreads();
    for (int s = 128; s > 0; s >>= 1) {
        if (threadIdx.x < s) red[threadIdx.x] += red[threadIdx.x + s];
        __syncthreads();
    }
    __shared__ float inv;
    if (threadIdx.x == 0) inv = rsqrtf(red[0] * (1.f / 2048.f) + 1e-6f);
    __syncthreads();
    float iv = inv;
    for (int i = threadIdx.x; i < 2048; i += 256) {
        float v = xr[i] * iv * w[i];
        size_t o = (size_t)row * 2048 + i;
        y[o] = v;
        __nv_bfloat16 h = __float2bfloat16(v);
        yhi[o] = h;
        ylo[o] = __float2bfloat16(v - __bfloat162float(h));
    }
}

// -------------------- orchestration --------------------
static const int SMEM_GEMM = 3 * 32768;          // 96KB
static const int SMEM_ATTN = 16384 + 3 * 16384;  // 64KB

extern "C" void kernel_launch(void* const* d_in, const int* in_sizes, int n_in,
                              void* d_out, int out_size)
{
    (void)in_sizes; (void)n_in; (void)out_size;
    const float* hidden      = (const float*)d_in[0];
    const float* comp_w      = (const float*)d_in[1];
    const float* comp_b      = (const float*)d_in[2];
    const float* q_w         = (const float*)d_in[3];
    const float* k_w         = (const float*)d_in[4];
    const float* v_w         = (const float*)d_in[5];
    const float* o_w         = (const float*)d_in[6];
    const float* attn_norm_w = (const float*)d_in[7];
    const float* mlp_norm_w  = (const float*)d_in[8];
    const float* gate_w      = (const float*)d_in[9];
    const float* up_w        = (const float*)d_in[10];
    const float* down_w      = (const float*)d_in[11];
    float* out = (float*)d_out;

    cudaFuncSetAttribute(bgemm<1,2>, cudaFuncAttributeMaxDynamicSharedMemorySize, SMEM_GEMM);
    cudaFuncSetAttribute(bgemm<0,1>, cudaFuncAttributeMaxDynamicSharedMemorySize, SMEM_GEMM);
    cudaFuncSetAttribute(bgemm<2,0>, cudaFuncAttributeMaxDynamicSharedMemorySize, SMEM_GEMM);
    cudaFuncSetAttribute(bgemm<2,2>, cudaFuncAttributeMaxDynamicSharedMemorySize, SMEM_GEMM);
    cudaFuncSetAttribute(bgemm<0,0>, cudaFuncAttributeMaxDynamicSharedMemorySize, SMEM_GEMM);
    cudaFuncSetAttribute(bgemm<3,1>, cudaFuncAttributeMaxDynamicSharedMemorySize, SMEM_GEMM);
    cudaFuncSetAttribute(bgemm_kv,   cudaFuncAttributeMaxDynamicSharedMemorySize, SMEM_GEMM);
    cudaFuncSetAttribute(attn_mma,   cudaFuncAttributeMaxDynamicSharedMemorySize, SMEM_ATTN);

    float *compressed, *ct, *gate;
    cudaGetSymbolAddress((void**)&compressed, g_compressed);
    cudaGetSymbolAddress((void**)&ct,         g_ct);
    cudaGetSymbolAddress((void**)&gate,       g_gate);

    __nv_bfloat16 *res_hi, *res_lo, *ct_hi, *ct_lo, *ao_hi, *ao_lo, *ga_hi, *ga_lo,
                  *hT_hi, *hT_lo, *q_hi, *q_lo, *k_hi, *k_lo, *v_hi, *v_lo,
                  *cw_hi, *cw_lo, *qw_hi, *qw_lo, *kw_hi, *kw_lo,
                  *vw_hi, *vw_lo, *ow_hi, *ow_lo, *gw_hi, *gw_lo, *uw_hi, *uw_lo,
                  *dw_hi, *dw_lo;
    cudaGetSymbolAddress((void**)&res_hi, g_res_hi); cudaGetSymbolAddress((void**)&res_lo, g_res_lo);
    cudaGetSymbolAddress((void**)&ct_hi,  g_ct_hi);  cudaGetSymbolAddress((void**)&ct_lo,  g_ct_lo);
    cudaGetSymbolAddress((void**)&ao_hi,  g_ao_hi);  cudaGetSymbolAddress((void**)&ao_lo,  g_ao_lo);
    cudaGetSymbolAddress((void**)&ga_hi,  g_ga_hi);  cudaGetSymbolAddress((void**)&ga_lo,  g_ga_lo);
    cudaGetSymbolAddress((void**)&hT_hi,  g_hT_hi);  cudaGetSymbolAddress((void**)&hT_lo,  g_hT_lo);
    cudaGetSymbolAddress((void**)&q_hi,   g_q_hi);   cudaGetSymbolAddress((void**)&q_lo,   g_q_lo);
    cudaGetSymbolAddress((void**)&k_hi,   g_k_hi);   cudaGetSymbolAddress((void**)&k_lo,   g_k_lo);
    cudaGetSymbolAddress((void**)&v_hi,   g_v_hi);   cudaGetSymbolAddress((void**)&v_lo,   g_v_lo);
    cudaGetSymbolAddress((void**)&cw_hi,  g_cw_hi);  cudaGetSymbolAddress((void**)&cw_lo,  g_cw_lo);
    cudaGetSymbolAddress((void**)&qw_hi,  g_qw_hi);  cudaGetSymbolAddress((void**)&qw_lo,  g_qw_lo);
    cudaGetSymbolAddress((void**)&kw_hi,  g_kw_hi);  cudaGetSymbolAddress((void**)&kw_lo,  g_kw_lo);
    cudaGetSymbolAddress((void**)&vw_hi,  g_vw_hi);  cudaGetSymbolAddress((void**)&vw_lo,  g_vw_lo);
    cudaGetSymbolAddress((void**)&ow_hi,  g_ow_hi);  cudaGetSymbolAddress((void**)&ow_lo,  g_ow_lo);
    cudaGetSymbolAddress((void**)&gw_hi,  g_gw_hi);  cudaGetSymbolAddress((void**)&gw_lo,  g_gw_lo);
    cudaGetSymbolAddress((void**)&uw_hi,  g_uw_hi);  cudaGetSymbolAddress((void**)&uw_lo,  g_uw_lo);
    cudaGetSymbolAddress((void**)&dw_hi,  g_dw_hi);  cudaGetSymbolAddress((void**)&dw_lo,  g_dw_lo);

    auto split = [&](const float* src, __nv_bfloat16* hi, __nv_bfloat16* lo, int n) {
        int n4 = n / 4;
        split_kernel<<<(n4 + 1023) / 1024, 256>>>(src, hi, lo, n4);
    };

    split(comp_w, cw_hi, cw_lo, 1024 * 2048);
    split(q_w,    qw_hi, qw_lo, 2048 * 2048);
    split(k_w,    kw_hi, kw_lo, 512 * 2048);
    split(v_w,    vw_hi, vw_lo, 512 * 2048);
    split(o_w,    ow_hi, ow_lo, 2048 * 2048);
    split(gate_w, gw_hi, gw_lo, 5632 * 2048);
    split(up_w,   uw_hi, uw_lo, 5632 * 2048);
    split(down_w, dw_hi, dw_lo, 2048 * 5632);
    transpose_split<<<dim3(64, 64), dim3(32, 8)>>>(hidden, hT_hi, hT_lo, 2048, 2048);
    split(hidden, res_hi, res_lo, 2048 * 2048);

    // compressed = comp_w @ hidden + comp_b ; also emit residual split rows
    bgemm<1,2><<<dim3(16, 8), 256, SMEM_GEMM>>>(cw_hi, cw_lo, hT_hi, hT_lo,
        compressed, comp_b, res_hi + 2048 * 2048, res_lo + 2048 * 2048,
        1024, 2048, 2048);

    for (int layer = 0; layer < 2; layer++) {
        rmsnorm_kernel<<<1024, 256>>>(compressed, attn_norm_w, ct, ct_hi, ct_lo);

        bgemm<0,1><<<dim3(16, 8), 256, SMEM_GEMM>>>(ct_hi, ct_lo, qw_hi, qw_lo,
            nullptr, nullptr, q_hi, q_lo, 1024, 2048, 2048);
        bgemm_kv<<<dim3(4, 24, 2), 256, SMEM_GEMM>>>(res_hi, res_lo,
            kw_hi, kw_lo, k_hi, k_lo, vw_hi, vw_lo, v_hi, v_lo, 3072, 512, 2048);

        attn_mma<<<dim3(16, 32), 128, SMEM_ATTN>>>(q_hi, q_lo, k_hi, k_lo,
                                                   v_hi, v_lo, ao_hi, ao_lo);

        // compressed = attno @ o_w^T + ct
        bgemm<2,0><<<dim3(16, 8), 256, SMEM_GEMM>>>(ao_hi, ao_lo, ow_hi, ow_lo,
            compressed, ct, nullptr, nullptr, 1024, 2048, 2048);

        rmsnorm_kernel<<<1024, 256>>>(compressed, mlp_norm_w, ct, ct_hi, ct_lo);

        // gate fp32, then up with fused silu(gate)*up -> hi/lo split
        bgemm<0,0><<<dim3(44, 8), 256, SMEM_GEMM>>>(ct_hi, ct_lo, gw_hi, gw_lo,
            gate, nullptr, nullptr, nullptr, 1024, 5632, 2048);
        bgemm<3,1><<<dim3(44, 8), 256, SMEM_GEMM>>>(ct_hi, ct_lo, uw_hi, uw_lo,
            nullptr, gate, ga_hi, ga_lo, 1024, 5632, 2048);

        // down-proj (+ct2). Layer0: also emit next layer's residual split rows.
        if (layer == 0) {
            bgemm<2,2><<<dim3(16, 8), 256, SMEM_GEMM>>>(ga_hi, ga_lo, dw_hi, dw_lo,
                compressed, ct, res_hi + 2048 * 2048, res_lo + 2048 * 2048,
                1024, 2048, 5632);
        } else {
            bgemm<2,0><<<dim3(16, 8), 256, SMEM_GEMM>>>(ga_hi, ga_lo, dw_hi, dw_lo,
                out, ct, nullptr, nullptr, 1024, 2048, 5632);
        }
    }
}

// round 8
// speedup vs baseline: 3.7381x; 1.1354x over previous
#include <cuda_runtime.h>
#include <cuda_bf16.h>
#include <cstdint>
#include <math.h>

// ===========================================================================
// S=2048, H=2048, COMP=1024, T=3072, KV_DIM=512, FF=5632, NH=32, NKV=8,
// HD=64, DEPTH=2. mma.sync.m16n8k16 bf16 hi/lo 3-product split everywhere.
// R7: conflict-free smem swizzle; merged q+k+v and gate+up launches.
// ===========================================================================

// -------------------- device-global scratch (no allocs) --------------------
__device__ float g_compressed[1024 * 2048];
__device__ float g_ct[1024 * 2048];
__device__ float g_gate[1024 * 5632];
__device__ float g_up[1024 * 5632];

__device__ __nv_bfloat16 g_res_hi[3072 * 2048], g_res_lo[3072 * 2048];
__device__ __nv_bfloat16 g_ct_hi[1024 * 2048], g_ct_lo[1024 * 2048];
__device__ __nv_bfloat16 g_ao_hi[1024 * 2048], g_ao_lo[1024 * 2048];
__device__ __nv_bfloat16 g_ga_hi[1024 * 5632], g_ga_lo[1024 * 5632];
__device__ __nv_bfloat16 g_hT_hi[2048 * 2048], g_hT_lo[2048 * 2048];

__device__ __nv_bfloat16 g_q_hi[1024 * 2048], g_q_lo[1024 * 2048];
__device__ __nv_bfloat16 g_k_hi[3072 * 512],  g_k_lo[3072 * 512];
__device__ __nv_bfloat16 g_v_hi[3072 * 512],  g_v_lo[3072 * 512];

__device__ __nv_bfloat16 g_cw_hi[1024 * 2048], g_cw_lo[1024 * 2048];
__device__ __nv_bfloat16 g_qw_hi[2048 * 2048], g_qw_lo[2048 * 2048];
__device__ __nv_bfloat16 g_kw_hi[512 * 2048],  g_kw_lo[512 * 2048];
__device__ __nv_bfloat16 g_vw_hi[512 * 2048],  g_vw_lo[512 * 2048];
__device__ __nv_bfloat16 g_ow_hi[2048 * 2048], g_ow_lo[2048 * 2048];
__device__ __nv_bfloat16 g_gw_hi[5632 * 2048], g_gw_lo[5632 * 2048];
__device__ __nv_bfloat16 g_uw_hi[5632 * 2048], g_uw_lo[5632 * 2048];
__device__ __nv_bfloat16 g_dw_hi[2048 * 5632], g_dw_lo[2048 * 5632];

// -------------------- helpers --------------------
__device__ __forceinline__ uint32_t smem_u32(const void* p) {
    return (uint32_t)__cvta_generic_to_shared(p);
}

#define LDSM_X4(r0, r1, r2, r3, addr)                                          \
    asm volatile("ldmatrix.sync.aligned.m8n8.x4.shared.b16 {%0,%1,%2,%3}, [%4];" \
                 : "=r"(r0), "=r"(r1), "=r"(r2), "=r"(r3) : "r"(addr))
#define LDSM_X4_T(r0, r1, r2, r3, addr)                                        \
    asm volatile("ldmatrix.sync.aligned.m8n8.x4.trans.shared.b16 {%0,%1,%2,%3}, [%4];" \
                 : "=r"(r0), "=r"(r1), "=r"(r2), "=r"(r3) : "r"(addr))

#define MMA_BF16(ac, ar, br)                                                   \
    asm volatile(                                                              \
        "mma.sync.aligned.m16n8k16.row.col.f32.bf16.bf16.f32 "                 \
        "{%0,%1,%2,%3},{%4,%5,%6,%7},{%8,%9},{%0,%1,%2,%3};"                   \
        : "+f"((ac)[0]), "+f"((ac)[1]), "+f"((ac)[2]), "+f"((ac)[3])           \
        : "r"((ar)[0]), "r"((ar)[1]), "r"((ar)[2]), "r"((ar)[3]),              \
          "r"((br)[0]), "r"((br)[1]))

#define CP_ASYNC16(dst, src)                                                   \
    asm volatile("cp.async.cg.shared.global [%0], [%1], 16;" :: "r"(dst), "l"(src))
#define CP_COMMIT() asm volatile("cp.async.commit_group;")
#define CP_WAIT1()  asm volatile("cp.async.wait_group 1;")

__device__ __forceinline__ uint32_t pack_bf2(float x, float y) {
    __nv_bfloat162 h = __floats2bfloat162_rn(x, y);
    return *(uint32_t*)&h;
}

// ==================== HMMA split-bf16 GEMM body ====================
// C = (Ahi+Alo)[M,K] @ (Bhi+Blo)[N,K]^T. BM=BN=128, BK=32, 3-stage cp.async.
// Swizzle (conflict-free): col16B-chunk XOR ((row>>1)&3)<<4 on 64B rows.
// EPI: 0 none, 1 +aux[row], 2 +aux[row*N+col]
// OUT: 0 fp32 C; 1 bf16 hi/lo; 2 both
__device__ __forceinline__ void load_stage(
    uint32_t sb, int kc, int tid, int m0, int n0, int K,
    const __nv_bfloat16* __restrict__ Ahi, const __nv_bfloat16* __restrict__ Alo,
    const __nv_bfloat16* __restrict__ Bhi, const __nv_bfloat16* __restrict__ Blo)
{
    const int kb = kc * 32;
#pragma unroll
    for (int i = 0; i < 2; i++) {
        int f = tid + i * 256;
        int r = f >> 2, c = f & 3;
        uint32_t off = (uint32_t)(r * 64) +
                       (uint32_t)((c * 16) ^ (((r >> 1) & 3) << 4));
        size_t ga = (size_t)(m0 + r) * K + kb + c * 8;
        size_t gb = (size_t)(n0 + r) * K + kb + c * 8;
        CP_ASYNC16(sb + off,         Ahi + ga);
        CP_ASYNC16(sb + 8192 + off,  Alo + ga);
        CP_ASYNC16(sb + 16384 + off, Bhi + gb);
        CP_ASYNC16(sb + 24576 + off, Blo + gb);
    }
}

template <int EPI, int OUT>
__device__ __forceinline__ void bgemm_body(
    const __nv_bfloat16* __restrict__ Ahi, const __nv_bfloat16* __restrict__ Alo,
    const __nv_bfloat16* __restrict__ Bhi, const __nv_bfloat16* __restrict__ Blo,
    float* __restrict__ C, const float* __restrict__ aux,
    __nv_bfloat16* __restrict__ Chi, __nv_bfloat16* __restrict__ Clo,
    int M, int N, int K, int m0, int n0)
{
    extern __shared__ char dsm[];
    const int tid = threadIdx.x;
    const int wid = tid >> 5, lid = tid & 31;
    const int wm = wid & 3, wn = wid >> 2;
    const uint32_t sbase = smem_u32(dsm);

    const int arow = wm * 32 + (lid & 7) + ((lid >> 3) & 1) * 8;
    const uint32_t a_base = (uint32_t)(arow * 64);
    const uint32_t a_sw = (uint32_t)(((arow >> 1) & 3) << 4);
    const uint32_t a_k = (uint32_t)((lid >> 4) & 1) * 16;

    const int brow = wn * 64 + (lid & 7) + ((lid >> 4) & 1) * 8;
    const uint32_t b_base = (uint32_t)(brow * 64);
    const uint32_t b_sw = (uint32_t)(((brow >> 1) & 3) << 4);
    const uint32_t b_k = (uint32_t)((lid >> 3) & 1) * 16;

    float acc[2][8][4];
#pragma unroll
    for (int mt = 0; mt < 2; mt++)
#pragma unroll
        for (int nt = 0; nt < 8; nt++)
#pragma unroll
            for (int e = 0; e < 4; e++) acc[mt][nt][e] = 0.f;

    const int NK = K / 32;
    load_stage(sbase, 0, tid, m0, n0, K, Ahi, Alo, Bhi, Blo);
    CP_COMMIT();
    load_stage(sbase + 32768, 1, tid, m0, n0, K, Ahi, Alo, Bhi, Blo);
    CP_COMMIT();

    for (int kc = 0; kc < NK; kc++) {
        CP_WAIT1();
        __syncthreads();
        if (kc + 2 < NK)
            load_stage(sbase + (uint32_t)((kc + 2) % 3) * 32768, kc + 2, tid,
                       m0, n0, K, Ahi, Alo, Bhi, Blo);
        CP_COMMIT();

        const uint32_t st = sbase + (uint32_t)(kc % 3) * 32768;
#pragma unroll
        for (int ks = 0; ks < 2; ks++) {
            const uint32_t ako = (a_k + (uint32_t)ks * 32) ^ a_sw;
            const uint32_t bko = (b_k + (uint32_t)ks * 32) ^ b_sw;
            uint32_t ah[2][4], al[2][4], bb[8][2];
#pragma unroll
            for (int mt = 0; mt < 2; mt++) {
                LDSM_X4(ah[mt][0], ah[mt][1], ah[mt][2], ah[mt][3],
                        st + a_base + (uint32_t)mt * 1024 + ako);
                LDSM_X4(al[mt][0], al[mt][1], al[mt][2], al[mt][3],
                        st + 8192 + a_base + (uint32_t)mt * 1024 + ako);
            }
#pragma unroll
            for (int p = 0; p < 4; p++) {
                LDSM_X4(bb[2*p][0], bb[2*p][1], bb[2*p+1][0], bb[2*p+1][1],
                        st + 16384 + b_base + (uint32_t)p * 1024 + bko);
            }
#pragma unroll
            for (int nt = 0; nt < 8; nt++)
#pragma unroll
                for (int mt = 0; mt < 2; mt++)
                    MMA_BF16(acc[mt][nt], ah[mt], bb[nt]);
#pragma unroll
            for (int nt = 0; nt < 8; nt++)
#pragma unroll
                for (int mt = 0; mt < 2; mt++)
                    MMA_BF16(acc[mt][nt], al[mt], bb[nt]);
#pragma unroll
            for (int p = 0; p < 4; p++) {
                LDSM_X4(bb[2*p][0], bb[2*p][1], bb[2*p+1][0], bb[2*p+1][1],
                        st + 24576 + b_base + (uint32_t)p * 1024 + bko);
            }
#pragma unroll
            for (int nt = 0; nt < 8; nt++)
#pragma unroll
                for (int mt = 0; mt < 2; mt++)
                    MMA_BF16(acc[mt][nt], ah[mt], bb[nt]);
        }
    }

    const int grow0 = m0 + wm * 32 + (lid >> 2);
    const int gcol0 = n0 + wn * 64 + (lid & 3) * 2;
#pragma unroll
    for (int mt = 0; mt < 2; mt++) {
#pragma unroll
        for (int nt = 0; nt < 8; nt++) {
            int r0 = grow0 + mt * 16;
            int c0 = gcol0 + nt * 8;
            float2 v0 = make_float2(acc[mt][nt][0], acc[mt][nt][1]);
            float2 v1 = make_float2(acc[mt][nt][2], acc[mt][nt][3]);
            if (EPI == 1) {
                float b0 = aux[r0], b1 = aux[r0 + 8];
                v0.x += b0; v0.y += b0; v1.x += b1; v1.y += b1;
            }
            if (EPI == 2) {
                const float2 a0 = *(const float2*)(aux + (size_t)r0 * N + c0);
                const float2 a1 = *(const float2*)(aux + (size_t)(r0 + 8) * N + c0);
                v0.x += a0.x; v0.y += a0.y; v1.x += a1.x; v1.y += a1.y;
            }
            if (OUT == 0 || OUT == 2) {
                *(float2*)(C + (size_t)r0 * N + c0) = v0;
                *(float2*)(C + (size_t)(r0 + 8) * N + c0) = v1;
            }
            if (OUT == 1 || OUT == 2) {
                uint32_t h0 = pack_bf2(v0.x, v0.y);
                uint32_t h1 = pack_bf2(v1.x, v1.y);
                *(uint32_t*)(Chi + (size_t)r0 * N + c0) = h0;
                *(uint32_t*)(Chi + (size_t)(r0 + 8) * N + c0) = h1;
                __nv_bfloat162 hh0 = *(__nv_bfloat162*)&h0;
                __nv_bfloat162 hh1 = *(__nv_bfloat162*)&h1;
                *(uint32_t*)(Clo + (size_t)r0 * N + c0) =
                    pack_bf2(v0.x - __bfloat162float(hh0.x),
                             v0.y - __bfloat162float(hh0.y));
                *(uint32_t*)(Clo + (size_t)(r0 + 8) * N + c0) =
                    pack_bf2(v1.x - __bfloat162float(hh1.x),
                             v1.y - __bfloat162float(hh1.y));
            }
        }
    }
}

template <int EPI, int OUT>
__global__ __launch_bounds__(256, 2) void bgemm(
    const __nv_bfloat16* __restrict__ Ahi, const __nv_bfloat16* __restrict__ Alo,
    const __nv_bfloat16* __restrict__ Bhi, const __nv_bfloat16* __restrict__ Blo,
    float* __restrict__ C, const float* __restrict__ aux,
    __nv_bfloat16* __restrict__ Chi, __nv_bfloat16* __restrict__ Clo,
    int M, int N, int K)
{
    bgemm_body<EPI, OUT>(Ahi, Alo, Bhi, Blo, C, aux, Chi, Clo, M, N, K,
                         blockIdx.y * 128, blockIdx.x * 128);
}

// q + k + v projections in ONE launch. 1-D grid of 320 tiles:
//   [0,128): q tiles  (M=1024, N=2048, A=ct)
//   [128,224): k tiles (M=3072, N=512, A=res)
//   [224,320): v tiles
__global__ __launch_bounds__(256, 2) void bgemm_qkv(
    const __nv_bfloat16* __restrict__ ct_hi, const __nv_bfloat16* __restrict__ ct_lo,
    const __nv_bfloat16* __restrict__ res_hi, const __nv_bfloat16* __restrict__ res_lo,
    const __nv_bfloat16* __restrict__ qw_hi, const __nv_bfloat16* __restrict__ qw_lo,
    const __nv_bfloat16* __restrict__ kw_hi, const __nv_bfloat16* __restrict__ kw_lo,
    const __nv_bfloat16* __restrict__ vw_hi, const __nv_bfloat16* __restrict__ vw_lo,
    __nv_bfloat16* __restrict__ q_hi, __nv_bfloat16* __restrict__ q_lo,
    __nv_bfloat16* __restrict__ k_hi, __nv_bfloat16* __restrict__ k_lo,
    __nv_bfloat16* __restrict__ v_hi, __nv_bfloat16* __restrict__ v_lo)
{
    int id = blockIdx.x;
    if (id < 128) {
        bgemm_body<0, 1>(ct_hi, ct_lo, qw_hi, qw_lo, nullptr, nullptr,
                         q_hi, q_lo, 1024, 2048, 2048,
                         (id >> 4) * 128, (id & 15) * 128);
    } else if (id < 224) {
        id -= 128;
        bgemm_body<0, 1>(res_hi, res_lo, kw_hi, kw_lo, nullptr, nullptr,
                         k_hi, k_lo, 3072, 512, 2048,
                         (id >> 2) * 128, (id & 3) * 128);
    } else {
        id -= 224;
        bgemm_body<0, 1>(res_hi, res_lo, vw_hi, vw_lo, nullptr, nullptr,
                         v_hi, v_lo, 3072, 512, 2048,
                         (id >> 2) * 128, (id & 3) * 128);
    }
}

// gate + up projections in ONE launch. 1-D grid of 704 tiles (both fp32 out).
__global__ __launch_bounds__(256, 2) void bgemm_gateup(
    const __nv_bfloat16* __restrict__ ct_hi, const __nv_bfloat16* __restrict__ ct_lo,
    const __nv_bfloat16* __restrict__ gw_hi, const __nv_bfloat16* __restrict__ gw_lo,
    const __nv_bfloat16* __restrict__ uw_hi, const __nv_bfloat16* __restrict__ uw_lo,
    float* __restrict__ gate, float* __restrict__ up)
{
    int id = blockIdx.x;
    if (id < 352) {
        bgemm_body<0, 0>(ct_hi, ct_lo, gw_hi, gw_lo, gate, nullptr,
                         nullptr, nullptr, 1024, 5632, 2048,
                         (id / 44) * 128, (id % 44) * 128);
    } else {
        id -= 352;
        bgemm_body<0, 0>(ct_hi, ct_lo, uw_hi, uw_lo, up, nullptr,
                         nullptr, nullptr, 1024, 5632, 2048,
                         (id / 44) * 128, (id % 44) * 128);
    }
}

// ==================== HMMA split-bf16 flash attention ====================
__global__ __launch_bounds__(128, 3) void attn_mma(
    const __nv_bfloat16* __restrict__ Qhi, const __nv_bfloat16* __restrict__ Qlo,
    const __nv_bfloat16* __restrict__ Khi, const __nv_bfloat16* __restrict__ Klo,
    const __nv_bfloat16* __restrict__ Vhi, const __nv_bfloat16* __restrict__ Vlo,
    __nv_bfloat16* __restrict__ Ohi, __nv_bfloat16* __restrict__ Olo)
{
    extern __shared__ char sm[];
    const int tid = threadIdx.x;
    const int wid = tid >> 5, lid = tid & 31;
    const int q0 = blockIdx.x * 64;
    const int head = blockIdx.y;
    const int kvoff = (head >> 2) * 64;
    const uint32_t sb = smem_u32(sm);
    const uint32_t sQh = sb, sQl = sb + 8192;
    const uint32_t sKV = sb + 16384;

#pragma unroll
    for (int i = 0; i < 4; i++) {
        int f = tid + i * 128;
        int r = f >> 3, c = f & 7;
        uint32_t off = (uint32_t)(r * 128) + (uint32_t)((c * 16) ^ ((r & 7) << 4));
        size_t g = (size_t)(q0 + r) * 2048 + head * 64 + c * 8;
        CP_ASYNC16(sQh + off, Qhi + g);
        CP_ASYNC16(sQl + off, Qlo + g);
    }
    CP_COMMIT();

#define ISSUE_KV(t0, st)                                                       \
    {                                                                          \
        uint32_t s_ = sKV + (uint32_t)(st) * 16384;                            \
        _Pragma("unroll")                                                      \
        for (int i_ = 0; i_ < 2; i_++) {                                       \
            int f_ = tid + i_ * 128;                                           \
            int r_ = f_ >> 3, c_ = f_ & 7;                                     \
            uint32_t o_ = (uint32_t)(r_ * 128) +                               \
                          (uint32_t)((c_ * 16) ^ ((r_ & 7) << 4));             \
            size_t g_ = (size_t)((t0) + r_) * 512 + kvoff + c_ * 8;            \
            CP_ASYNC16(s_ + o_,         Khi + g_);                             \
            CP_ASYNC16(s_ + 4096 + o_,  Klo + g_);                             \
            CP_ASYNC16(s_ + 8192 + o_,  Vhi + g_);                             \
            CP_ASYNC16(s_ + 12288 + o_, Vlo + g_);                             \
        }                                                                      \
    }

    ISSUE_KV(0, 0);  CP_COMMIT();
    ISSUE_KV(32, 1); CP_COMMIT();

    asm volatile("cp.async.wait_group 2;");
    __syncthreads();

    uint32_t qh[4][4], ql[4][4];
    {
        const int ar = (lid & 7) + ((lid >> 3) & 1) * 8;
        const int row = wid * 16 + ar;
        const uint32_t khalf = (uint32_t)((lid >> 4) & 1) * 16;
#pragma unroll
        for (int ks = 0; ks < 4; ks++) {
            uint32_t off = (uint32_t)(row * 128) +
                           ((khalf + (uint32_t)ks * 32) ^ ((uint32_t)(ar & 7) << 4));
            LDSM_X4(qh[ks][0], qh[ks][1], qh[ks][2], qh[ks][3], sQh + off);
            LDSM_X4(ql[ks][0], ql[ks][1], ql[ks][2], ql[ks][3], sQl + off);
        }
    }

    float acc_o[8][4];
#pragma unroll
    for (int d = 0; d < 8; d++)
#pragma unroll
        for (int e = 0; e < 4; e++) acc_o[d][e] = 0.f;
    float mr0 = -1e30f, mr1 = -1e30f, lr0 = 0.f, lr1 = 0.f;

    const int brS = (lid & 7) + ((lid >> 4) & 1) * 8;
    const uint32_t bkS = (uint32_t)((lid >> 3) & 1) * 16;
    const int trV = (lid & 7) + ((lid >> 3) & 1) * 8;
    const uint32_t dkV = (uint32_t)((lid >> 4) & 1) * 16;

    for (int t = 0; t < 96; t++) {
        if (t + 1 < 96) { CP_WAIT1(); } else { asm volatile("cp.async.wait_group 0;"); }
        __syncthreads();
        if (t + 2 < 96) ISSUE_KV((t + 2) * 32, (t + 2) % 3);
        CP_COMMIT();
        const uint32_t st = sKV + (uint32_t)(t % 3) * 16384;

        float s[4][4];
#pragma unroll
        for (int nt = 0; nt < 4; nt++)
#pragma unroll
            for (int e = 0; e < 4; e++) s[nt][e] = 0.f;
#pragma unroll
        for (int ks = 0; ks < 4; ks++) {
            uint32_t bh[4][2], bl[4][2];
#pragma unroll
            for (int p = 0; p < 2; p++) {
                int rr = p * 16 + brS;
                uint32_t off = (uint32_t)(rr * 128) +
                               ((bkS + (uint32_t)ks * 32) ^ ((uint32_t)(rr & 7) << 4));
                LDSM_X4(bh[2*p][0], bh[2*p][1], bh[2*p+1][0], bh[2*p+1][1], st + off);
                LDSM_X4(bl[2*p][0], bl[2*p][1], bl[2*p+1][0], bl[2*p+1][1], st + 4096 + off);
            }
#pragma unroll
            for (int nt = 0; nt < 4; nt++) {
                MMA_BF16(s[nt], qh[ks], bh[nt]);
                MMA_BF16(s[nt], qh[ks], bl[nt]);
                MMA_BF16(s[nt], ql[ks], bh[nt]);
            }
        }

        float mn0 = mr0, mn1 = mr1;
#pragma unroll
        for (int nt = 0; nt < 4; nt++) {
            s[nt][0] *= 0.125f; s[nt][1] *= 0.125f;
            s[nt][2] *= 0.125f; s[nt][3] *= 0.125f;
            mn0 = fmaxf(mn0, fmaxf(s[nt][0], s[nt][1]));
            mn1 = fmaxf(mn1, fmaxf(s[nt][2], s[nt][3]));
        }
        mn0 = fmaxf(mn0, __shfl_xor_sync(0xffffffffu, mn0, 1));
        mn0 = fmaxf(mn0, __shfl_xor_sync(0xffffffffu, mn0, 2));
        mn1 = fmaxf(mn1, __shfl_xor_sync(0xffffffffu, mn1, 1));
        mn1 = fmaxf(mn1, __shfl_xor_sync(0xffffffffu, mn1, 2));
        float f0 = __expf(mr0 - mn0), f1 = __expf(mr1 - mn1);
        mr0 = mn0; mr1 = mn1;
        float ps0 = 0.f, ps1 = 0.f;
#pragma unroll
        for (int nt = 0; nt < 4; nt++) {
            s[nt][0] = __expf(s[nt][0] - mn0);
            s[nt][1] = __expf(s[nt][1] - mn0);
            s[nt][2] = __expf(s[nt][2] - mn1);
            s[nt][3] = __expf(s[nt][3] - mn1);
            ps0 += s[nt][0] + s[nt][1];
            ps1 += s[nt][2] + s[nt][3];
        }
        lr0 = lr0 * f0 + ps0;
        lr1 = lr1 * f1 + ps1;
#pragma unroll
        for (int d = 0; d < 8; d++) {
            acc_o[d][0] *= f0; acc_o[d][1] *= f0;
            acc_o[d][2] *= f1; acc_o[d][3] *= f1;
        }

#pragma unroll
        for (int j = 0; j < 2; j++) {
            uint32_t ah[4], al[4];
            {
                float p00 = s[2*j][0],   p01 = s[2*j][1];
                float p02 = s[2*j][2],   p03 = s[2*j][3];
                float p10 = s[2*j+1][0], p11 = s[2*j+1][1];
                float p12 = s[2*j+1][2], p13 = s[2*j+1][3];
                ah[0] = pack_bf2(p00, p01); ah[1] = pack_bf2(p02, p03);
                ah[2] = pack_bf2(p10, p11); ah[3] = pack_bf2(p12, p13);
#pragma unroll
                for (int e = 0; e < 4; e++) {
                    __nv_bfloat162 hh = *(__nv_bfloat162*)&ah[e];
                    float x0, x1;
                    if (e == 0) { x0 = p00; x1 = p01; }
                    else if (e == 1) { x0 = p02; x1 = p03; }
                    else if (e == 2) { x0 = p10; x1 = p11; }
                    else { x0 = p12; x1 = p13; }
                    al[e] = pack_bf2(x0 - __bfloat162float(hh.x),
                                     x1 - __bfloat162float(hh.y));
                }
            }
            const int rr = j * 16 + trV;
#pragma unroll
            for (int dp = 0; dp < 4; dp++) {
                uint32_t off = (uint32_t)(rr * 128) +
                               ((dkV + (uint32_t)dp * 32) ^ ((uint32_t)(rr & 7) << 4));
                uint32_t vh[4], vl[4];
                LDSM_X4_T(vh[0], vh[1], vh[2], vh[3], st + 8192 + off);
                LDSM_X4_T(vl[0], vl[1], vl[2], vl[3], st + 12288 + off);
                uint32_t b0h[2] = {vh[0], vh[1]}, b1h[2] = {vh[2], vh[3]};
                uint32_t b0l[2] = {vl[0], vl[1]}, b1l[2] = {vl[2], vl[3]};
                MMA_BF16(acc_o[2*dp],   ah, b0h);
                MMA_BF16(acc_o[2*dp],   ah, b0l);
                MMA_BF16(acc_o[2*dp],   al, b0h);
                MMA_BF16(acc_o[2*dp+1], ah, b1h);
                MMA_BF16(acc_o[2*dp+1], ah, b1l);
                MMA_BF16(acc_o[2*dp+1], al, b1h);
            }
        }
    }

    lr0 += __shfl_xor_sync(0xffffffffu, lr0, 1);
    lr0 += __shfl_xor_sync(0xffffffffu, lr0, 2);
    lr1 += __shfl_xor_sync(0xffffffffu, lr1, 1);
    lr1 += __shfl_xor_sync(0xffffffffu, lr1, 2);
    float il0 = 1.f / lr0, il1 = 1.f / lr1;
    const int row0 = q0 + wid * 16 + (lid >> 2);
    const int col0 = head * 64 + (lid & 3) * 2;
#pragma unroll
    for (int d = 0; d < 8; d++) {
        int col = col0 + d * 8;
        float o0 = acc_o[d][0] * il0, o1 = acc_o[d][1] * il0;
        float o2 = acc_o[d][2] * il1, o3 = acc_o[d][3] * il1;
        uint32_t h0 = pack_bf2(o0, o1), h1 = pack_bf2(o2, o3);
        *(uint32_t*)(Ohi + (size_t)row0 * 2048 + col) = h0;
        *(uint32_t*)(Ohi + (size_t)(row0 + 8) * 2048 + col) = h1;
        __nv_bfloat162 hh0 = *(__nv_bfloat162*)&h0;
        __nv_bfloat162 hh1 = *(__nv_bfloat162*)&h1;
        *(uint32_t*)(Olo + (size_t)row0 * 2048 + col) =
            pack_bf2(o0 - __bfloat162float(hh0.x), o1 - __bfloat162float(hh0.y));
        *(uint32_t*)(Olo + (size_t)(row0 + 8) * 2048 + col) =
            pack_bf2(o2 - __bfloat162float(hh1.x), o3 - __bfloat162float(hh1.y));
    }
}

// -------------------- conversion / elementwise kernels --------------------
__global__ void split_kernel(const float* __restrict__ x,
                             __nv_bfloat16* __restrict__ hi,
                             __nv_bfloat16* __restrict__ lo, int n4)
{
    int i = blockIdx.x * 1024 + threadIdx.x;
#pragma unroll
    for (int u = 0; u < 4; u++, i += 256) {
        if (i < n4) {
            float4 v = ((const float4*)x)[i];
            __nv_bfloat16 h0 = __float2bfloat16(v.x), h1 = __float2bfloat16(v.y);
            __nv_bfloat16 h2 = __float2bfloat16(v.z), h3 = __float2bfloat16(v.w);
            __nv_bfloat162 ha; ha.x = h0; ha.y = h1;
            __nv_bfloat162 hb; hb.x = h2; hb.y = h3;
            ((__nv_bfloat162*)hi)[i * 2]     = ha;
            ((__nv_bfloat162*)hi)[i * 2 + 1] = hb;
            __nv_bfloat162 la, lb;
            la.x = __float2bfloat16(v.x - __bfloat162float(h0));
            la.y = __float2bfloat16(v.y - __bfloat162float(h1));
            lb.x = __float2bfloat16(v.z - __bfloat162float(h2));
            lb.y = __float2bfloat16(v.w - __bfloat162float(h3));
            ((__nv_bfloat162*)lo)[i * 2]     = la;
            ((__nv_bfloat162*)lo)[i * 2 + 1] = lb;
        }
    }
}

__global__ void transpose_split(const float* __restrict__ x,
                                __nv_bfloat16* __restrict__ hiT,
                                __nv_bfloat16* __restrict__ loT, int R, int C)
{
    __shared__ float t[32][33];
    int c0 = blockIdx.x * 32, r0 = blockIdx.y * 32;
    for (int i = threadIdx.y; i < 32; i += 8)
        t[i][threadIdx.x] = x[(size_t)(r0 + i) * C + c0 + threadIdx.x];
    __syncthreads();
    for (int i = threadIdx.y; i < 32; i += 8) {
        float v = t[threadIdx.x][i];
        __nv_bfloat16 h = __float2bfloat16(v);
        size_t o = (size_t)(c0 + i) * R + r0 + threadIdx.x;
        hiT[o] = h;
        loT[o] = __float2bfloat16(v - __bfloat162float(h));
    }
}

__global__ void rmsnorm_kernel(const float* __restrict__ x,
                               const float* __restrict__ w,
                               float* __restrict__ y,
                               __nv_bfloat16* __restrict__ yhi,
                               __nv_bfloat16* __restrict__ ylo)
{
    const int row = blockIdx.x;
    const float* xr = x + (size_t)row * 2048;
    float ss = 0.f;
    for (int i = threadIdx.x; i < 2048; i += 256) { float v = xr[i]; ss += v * v; }
    __shared__ float red[256];
    red[threadIdx.x] = ss;
    __syncthreads();
    for (int s = 128; s > 0; s >>= 1) {
        if (threadIdx.x < s) red[threadIdx.x] += red[threadIdx.x + s];
        __syncthreads();
    }
    __shared__ float inv;
    if (threadIdx.x == 0) inv = rsqrtf(red[0] * (1.f / 2048.f) + 1e-6f);
    __syncthreads();
    float iv = inv;
    for (int i = threadIdx.x; i < 2048; i += 256) {
        float v = xr[i] * iv * w[i];
        size_t o = (size_t)row * 2048 + i;
        y[o] = v;
        __nv_bfloat16 h = __float2bfloat16(v);
        yhi[o] = h;
        ylo[o] = __float2bfloat16(v - __bfloat162float(h));
    }
}

__global__ void swiglu_split(const float* __restrict__ g, const float* __restrict__ u,
                             __nv_bfloat16* __restrict__ hi, __nv_bfloat16* __restrict__ lo,
                             int n)
{
    int i = blockIdx.x * blockDim.x + threadIdx.x;
    if (i < n) {
        float x = g[i];
        float v = (x / (1.f + __expf(-x))) * u[i];
        __nv_bfloat16 h = __float2bfloat16(v);
        hi[i] = h;
        lo[i] = __float2bfloat16(v - __bfloat162float(h));
    }
}

// -------------------- orchestration --------------------
static const int SMEM_GEMM = 3 * 32768;          // 96KB
static const int SMEM_ATTN = 16384 + 3 * 16384;  // 64KB

extern "C" void kernel_launch(void* const* d_in, const int* in_sizes, int n_in,
                              void* d_out, int out_size)
{
    (void)in_sizes; (void)n_in; (void)out_size;
    const float* hidden      = (const float*)d_in[0];
    const float* comp_w      = (const float*)d_in[1];
    const float* comp_b      = (const float*)d_in[2];
    const float* q_w         = (const float*)d_in[3];
    const float* k_w         = (const float*)d_in[4];
    const float* v_w         = (const float*)d_in[5];
    const float* o_w         = (const float*)d_in[6];
    const float* attn_norm_w = (const float*)d_in[7];
    const float* mlp_norm_w  = (const float*)d_in[8];
    const float* gate_w      = (const float*)d_in[9];
    const float* up_w        = (const float*)d_in[10];
    const float* down_w      = (const float*)d_in[11];
    float* out = (float*)d_out;

    cudaFuncSetAttribute(bgemm<1,2>, cudaFuncAttributeMaxDynamicSharedMemorySize, SMEM_GEMM);
    cudaFuncSetAttribute(bgemm<2,0>, cudaFuncAttributeMaxDynamicSharedMemorySize, SMEM_GEMM);
    cudaFuncSetAttribute(bgemm<2,2>, cudaFuncAttributeMaxDynamicSharedMemorySize, SMEM_GEMM);
    cudaFuncSetAttribute(bgemm_qkv,    cudaFuncAttributeMaxDynamicSharedMemorySize, SMEM_GEMM);
    cudaFuncSetAttribute(bgemm_gateup, cudaFuncAttributeMaxDynamicSharedMemorySize, SMEM_GEMM);
    cudaFuncSetAttribute(attn_mma,     cudaFuncAttributeMaxDynamicSharedMemorySize, SMEM_ATTN);

    float *compressed, *ct, *gate, *up;
    cudaGetSymbolAddress((void**)&compressed, g_compressed);
    cudaGetSymbolAddress((void**)&ct,         g_ct);
    cudaGetSymbolAddress((void**)&gate,       g_gate);
    cudaGetSymbolAddress((void**)&up,         g_up);

    __nv_bfloat16 *res_hi, *res_lo, *ct_hi, *ct_lo, *ao_hi, *ao_lo, *ga_hi, *ga_lo,
                  *hT_hi, *hT_lo, *q_hi, *q_lo, *k_hi, *k_lo, *v_hi, *v_lo,
                  *cw_hi, *cw_lo, *qw_hi, *qw_lo, *kw_hi, *kw_lo,
                  *vw_hi, *vw_lo, *ow_hi, *ow_lo, *gw_hi, *gw_lo, *uw_hi, *uw_lo,
                  *dw_hi, *dw_lo;
    cudaGetSymbolAddress((void**)&res_hi, g_res_hi); cudaGetSymbolAddress((void**)&res_lo, g_res_lo);
    cudaGetSymbolAddress((void**)&ct_hi,  g_ct_hi);  cudaGetSymbolAddress((void**)&ct_lo,  g_ct_lo);
    cudaGetSymbolAddress((void**)&ao_hi,  g_ao_hi);  cudaGetSymbolAddress((void**)&ao_lo,  g_ao_lo);
    cudaGetSymbolAddress((void**)&ga_hi,  g_ga_hi);  cudaGetSymbolAddress((void**)&ga_lo,  g_ga_lo);
    cudaGetSymbolAddress((void**)&hT_hi,  g_hT_hi);  cudaGetSymbolAddress((void**)&hT_lo,  g_hT_lo);
    cudaGetSymbolAddress((void**)&q_hi,   g_q_hi);   cudaGetSymbolAddress((void**)&q_lo,   g_q_lo);
    cudaGetSymbolAddress((void**)&k_hi,   g_k_hi);   cudaGetSymbolAddress((void**)&k_lo,   g_k_lo);
    cudaGetSymbolAddress((void**)&v_hi,   g_v_hi);   cudaGetSymbolAddress((void**)&v_lo,   g_v_lo);
    cudaGetSymbolAddress((void**)&cw_hi,  g_cw_hi);  cudaGetSymbolAddress((void**)&cw_lo,  g_cw_lo);
    cudaGetSymbolAddress((void**)&qw_hi,  g_qw_hi);  cudaGetSymbolAddress((void**)&qw_lo,  g_qw_lo);
    cudaGetSymbolAddress((void**)&kw_hi,  g_kw_hi);  cudaGetSymbolAddress((void**)&kw_lo,  g_kw_lo);
    cudaGetSymbolAddress((void**)&vw_hi,  g_vw_hi);  cudaGetSymbolAddress((void**)&vw_lo,  g_vw_lo);
    cudaGetSymbolAddress((void**)&ow_hi,  g_ow_hi);  cudaGetSymbolAddress((void**)&ow_lo,  g_ow_lo);
    cudaGetSymbolAddress((void**)&gw_hi,  g_gw_hi);  cudaGetSymbolAddress((void**)&gw_lo,  g_gw_lo);
    cudaGetSymbolAddress((void**)&uw_hi,  g_uw_hi);  cudaGetSymbolAddress((void**)&uw_lo,  g_uw_lo);
    cudaGetSymbolAddress((void**)&dw_hi,  g_dw_hi);  cudaGetSymbolAddress((void**)&dw_lo,  g_dw_lo);

    auto split = [&](const float* src, __nv_bfloat16* hi, __nv_bfloat16* lo, int n) {
        int n4 = n / 4;
        split_kernel<<<(n4 + 1023) / 1024, 256>>>(src, hi, lo, n4);
    };

    split(comp_w, cw_hi, cw_lo, 1024 * 2048);
    split(q_w,    qw_hi, qw_lo, 2048 * 2048);
    split(k_w,    kw_hi, kw_lo, 512 * 2048);
    split(v_w,    vw_hi, vw_lo, 512 * 2048);
    split(o_w,    ow_hi, ow_lo, 2048 * 2048);
    split(gate_w, gw_hi, gw_lo, 5632 * 2048);
    split(up_w,   uw_hi, uw_lo, 5632 * 2048);
    split(down_w, dw_hi, dw_lo, 2048 * 5632);
    transpose_split<<<dim3(64, 64), dim3(32, 8)>>>(hidden, hT_hi, hT_lo, 2048, 2048);
    split(hidden, res_hi, res_lo, 2048 * 2048);

    // compressed = comp_w @ hidden + comp_b ; also emit residual split rows
    bgemm<1,2><<<dim3(16, 8), 256, SMEM_GEMM>>>(cw_hi, cw_lo, hT_hi, hT_lo,
        compressed, comp_b, res_hi + 2048 * 2048, res_lo + 2048 * 2048,
        1024, 2048, 2048);

    for (int layer = 0; layer < 2; layer++) {
        rmsnorm_kernel<<<1024, 256>>>(compressed, attn_norm_w, ct, ct_hi, ct_lo);

        bgemm_qkv<<<320, 256, SMEM_GEMM>>>(ct_hi, ct_lo, res_hi, res_lo,
            qw_hi, qw_lo, kw_hi, kw_lo, vw_hi, vw_lo,
            q_hi, q_lo, k_hi, k_lo, v_hi, v_lo);

        attn_mma<<<dim3(16, 32), 128, SMEM_ATTN>>>(q_hi, q_lo, k_hi, k_lo,
                                                   v_hi, v_lo, ao_hi, ao_lo);

        bgemm<2,0><<<dim3(16, 8), 256, SMEM_GEMM>>>(ao_hi, ao_lo, ow_hi, ow_lo,
            compressed, ct, nullptr, nullptr, 1024, 2048, 2048);

        rmsnorm_kernel<<<1024, 256>>>(compressed, mlp_norm_w, ct, ct_hi, ct_lo);

        bgemm_gateup<<<704, 256, SMEM_GEMM>>>(ct_hi, ct_lo, gw_hi, gw_lo,
                                              uw_hi, uw_lo, gate, up);
        swiglu_split<<<(1024 * 5632 + 255) / 256, 256>>>(gate, up, ga_hi, ga_lo,
                                                         1024 * 5632);

        if (layer == 0) {
            bgemm<2,2><<<dim3(16, 8), 256, SMEM_GEMM>>>(ga_hi, ga_lo, dw_hi, dw_lo,
                compressed, ct, res_hi + 2048 * 2048, res_lo + 2048 * 2048,
                1024, 2048, 5632);
        } else {
            bgemm<2,0><<<dim3(16, 8), 256, SMEM_GEMM>>>(ga_hi, ga_lo, dw_hi, dw_lo,
                out, ct, nullptr, nullptr, 1024, 2048, 5632);
        }
    }
}

// round 9
// speedup vs baseline: 3.8868x; 1.0398x over previous
#include <cuda_runtime.h>
#include <cuda_bf16.h>
#include <cstdint>
#include <math.h>

// ===========================================================================
// S=2048, H=2048, COMP=1024, T=3072, KV_DIM=512, FF=5632, NH=32, NKV=8,
// HD=64, DEPTH=2. mma.sync.m16n8k16 bf16 hi/lo 3-product split everywhere.
// R8: split-K x2 for low-CTA GEMMs (comp/o/down/kv) + fused reduce kernels;
//     attention 2-stage pipeline at 4 CTAs/SM (single wave).
// ===========================================================================

// -------------------- device-global scratch (no allocs) --------------------
__device__ float g_compressed[1024 * 2048];
__device__ float g_ct[1024 * 2048];
__device__ float g_gate[1024 * 5632];
__device__ float g_up[1024 * 5632];
__device__ float g_p0[1024 * 2048], g_p1[1024 * 2048];       // split-K partials
__device__ float g_pk0[3072 * 512], g_pk1[3072 * 512];
__device__ float g_pv0[3072 * 512], g_pv1[3072 * 512];

__device__ __nv_bfloat16 g_res_hi[3072 * 2048], g_res_lo[3072 * 2048];
__device__ __nv_bfloat16 g_ct_hi[1024 * 2048], g_ct_lo[1024 * 2048];
__device__ __nv_bfloat16 g_ao_hi[1024 * 2048], g_ao_lo[1024 * 2048];
__device__ __nv_bfloat16 g_ga_hi[1024 * 5632], g_ga_lo[1024 * 5632];
__device__ __nv_bfloat16 g_hT_hi[2048 * 2048], g_hT_lo[2048 * 2048];

__device__ __nv_bfloat16 g_q_hi[1024 * 2048], g_q_lo[1024 * 2048];
__device__ __nv_bfloat16 g_k_hi[3072 * 512],  g_k_lo[3072 * 512];
__device__ __nv_bfloat16 g_v_hi[3072 * 512],  g_v_lo[3072 * 512];

__device__ __nv_bfloat16 g_cw_hi[1024 * 2048], g_cw_lo[1024 * 2048];
__device__ __nv_bfloat16 g_qw_hi[2048 * 2048], g_qw_lo[2048 * 2048];
__device__ __nv_bfloat16 g_kw_hi[512 * 2048],  g_kw_lo[512 * 2048];
__device__ __nv_bfloat16 g_vw_hi[512 * 2048],  g_vw_lo[512 * 2048];
__device__ __nv_bfloat16 g_ow_hi[2048 * 2048], g_ow_lo[2048 * 2048];
__device__ __nv_bfloat16 g_gw_hi[5632 * 2048], g_gw_lo[5632 * 2048];
__device__ __nv_bfloat16 g_uw_hi[5632 * 2048], g_uw_lo[5632 * 2048];
__device__ __nv_bfloat16 g_dw_hi[2048 * 5632], g_dw_lo[2048 * 5632];

// -------------------- helpers --------------------
__device__ __forceinline__ uint32_t smem_u32(const void* p) {
    return (uint32_t)__cvta_generic_to_shared(p);
}

#define LDSM_X4(r0, r1, r2, r3, addr)                                          \
    asm volatile("ldmatrix.sync.aligned.m8n8.x4.shared.b16 {%0,%1,%2,%3}, [%4];" \
                 : "=r"(r0), "=r"(r1), "=r"(r2), "=r"(r3) : "r"(addr))
#define LDSM_X4_T(r0, r1, r2, r3, addr)                                        \
    asm volatile("ldmatrix.sync.aligned.m8n8.x4.trans.shared.b16 {%0,%1,%2,%3}, [%4];" \
                 : "=r"(r0), "=r"(r1), "=r"(r2), "=r"(r3) : "r"(addr))

#define MMA_BF16(ac, ar, br)                                                   \
    asm volatile(                                                              \
        "mma.sync.aligned.m16n8k16.row.col.f32.bf16.bf16.f32 "                 \
        "{%0,%1,%2,%3},{%4,%5,%6,%7},{%8,%9},{%0,%1,%2,%3};"                   \
        : "+f"((ac)[0]), "+f"((ac)[1]), "+f"((ac)[2]), "+f"((ac)[3])           \
        : "r"((ar)[0]), "r"((ar)[1]), "r"((ar)[2]), "r"((ar)[3]),              \
          "r"((br)[0]), "r"((br)[1]))

#define CP_ASYNC16(dst, src)                                                   \
    asm volatile("cp.async.cg.shared.global [%0], [%1], 16;" :: "r"(dst), "l"(src))
#define CP_COMMIT() asm volatile("cp.async.commit_group;")
#define CP_WAIT1()  asm volatile("cp.async.wait_group 1;")

__device__ __forceinline__ uint32_t pack_bf2(float x, float y) {
    __nv_bfloat162 h = __floats2bfloat162_rn(x, y);
    return *(uint32_t*)&h;
}

// ==================== HMMA split-bf16 GEMM body ====================
// C = (Ahi+Alo)[M,Klen] @ (Bhi+Blo)[N,Klen]^T (row stride K).
// BM=BN=128, BK=32, 3-stage cp.async, conflict-free swizzle.
// OUT: 0 fp32 C; 1 bf16 hi/lo split
__device__ __forceinline__ void load_stage(
    uint32_t sb, int kc, int tid, int m0, int n0, int K,
    const __nv_bfloat16* __restrict__ Ahi, const __nv_bfloat16* __restrict__ Alo,
    const __nv_bfloat16* __restrict__ Bhi, const __nv_bfloat16* __restrict__ Blo)
{
    const int kb = kc * 32;
#pragma unroll
    for (int i = 0; i < 2; i++) {
        int f = tid + i * 256;
        int r = f >> 2, c = f & 3;
        uint32_t off = (uint32_t)(r * 64) +
                       (uint32_t)((c * 16) ^ (((r >> 1) & 3) << 4));
        size_t ga = (size_t)(m0 + r) * K + kb + c * 8;
        size_t gb = (size_t)(n0 + r) * K + kb + c * 8;
        CP_ASYNC16(sb + off,         Ahi + ga);
        CP_ASYNC16(sb + 8192 + off,  Alo + ga);
        CP_ASYNC16(sb + 16384 + off, Bhi + gb);
        CP_ASYNC16(sb + 24576 + off, Blo + gb);
    }
}

template <int OUT>
__device__ __forceinline__ void bgemm_body(
    const __nv_bfloat16* __restrict__ Ahi, const __nv_bfloat16* __restrict__ Alo,
    const __nv_bfloat16* __restrict__ Bhi, const __nv_bfloat16* __restrict__ Blo,
    float* __restrict__ C,
    __nv_bfloat16* __restrict__ Chi, __nv_bfloat16* __restrict__ Clo,
    int N, int K, int Klen, int m0, int n0)
{
    extern __shared__ char dsm[];
    const int tid = threadIdx.x;
    const int wid = tid >> 5, lid = tid & 31;
    const int wm = wid & 3, wn = wid >> 2;
    const uint32_t sbase = smem_u32(dsm);

    const int arow = wm * 32 + (lid & 7) + ((lid >> 3) & 1) * 8;
    const uint32_t a_base = (uint32_t)(arow * 64);
    const uint32_t a_sw = (uint32_t)(((arow >> 1) & 3) << 4);
    const uint32_t a_k = (uint32_t)((lid >> 4) & 1) * 16;

    const int brow = wn * 64 + (lid & 7) + ((lid >> 4) & 1) * 8;
    const uint32_t b_base = (uint32_t)(brow * 64);
    const uint32_t b_sw = (uint32_t)(((brow >> 1) & 3) << 4);
    const uint32_t b_k = (uint32_t)((lid >> 3) & 1) * 16;

    float acc[2][8][4];
#pragma unroll
    for (int mt = 0; mt < 2; mt++)
#pragma unroll
        for (int nt = 0; nt < 8; nt++)
#pragma unroll
            for (int e = 0; e < 4; e++) acc[mt][nt][e] = 0.f;

    const int NK = Klen / 32;
    load_stage(sbase, 0, tid, m0, n0, K, Ahi, Alo, Bhi, Blo);
    CP_COMMIT();
    load_stage(sbase + 32768, 1, tid, m0, n0, K, Ahi, Alo, Bhi, Blo);
    CP_COMMIT();

    for (int kc = 0; kc < NK; kc++) {
        CP_WAIT1();
        __syncthreads();
        if (kc + 2 < NK)
            load_stage(sbase + (uint32_t)((kc + 2) % 3) * 32768, kc + 2, tid,
                       m0, n0, K, Ahi, Alo, Bhi, Blo);
        CP_COMMIT();

        const uint32_t st = sbase + (uint32_t)(kc % 3) * 32768;
#pragma unroll
        for (int ks = 0; ks < 2; ks++) {
            const uint32_t ako = (a_k + (uint32_t)ks * 32) ^ a_sw;
            const uint32_t bko = (b_k + (uint32_t)ks * 32) ^ b_sw;
            uint32_t ah[2][4], al[2][4], bb[8][2];
#pragma unroll
            for (int mt = 0; mt < 2; mt++) {
                LDSM_X4(ah[mt][0], ah[mt][1], ah[mt][2], ah[mt][3],
                        st + a_base + (uint32_t)mt * 1024 + ako);
                LDSM_X4(al[mt][0], al[mt][1], al[mt][2], al[mt][3],
                        st + 8192 + a_base + (uint32_t)mt * 1024 + ako);
            }
#pragma unroll
            for (int p = 0; p < 4; p++) {
                LDSM_X4(bb[2*p][0], bb[2*p][1], bb[2*p+1][0], bb[2*p+1][1],
                        st + 16384 + b_base + (uint32_t)p * 1024 + bko);
            }
#pragma unroll
            for (int nt = 0; nt < 8; nt++)
#pragma unroll
                for (int mt = 0; mt < 2; mt++)
                    MMA_BF16(acc[mt][nt], ah[mt], bb[nt]);
#pragma unroll
            for (int nt = 0; nt < 8; nt++)
#pragma unroll
                for (int mt = 0; mt < 2; mt++)
                    MMA_BF16(acc[mt][nt], al[mt], bb[nt]);
#pragma unroll
            for (int p = 0; p < 4; p++) {
                LDSM_X4(bb[2*p][0], bb[2*p][1], bb[2*p+1][0], bb[2*p+1][1],
                        st + 24576 + b_base + (uint32_t)p * 1024 + bko);
            }
#pragma unroll
            for (int nt = 0; nt < 8; nt++)
#pragma unroll
                for (int mt = 0; mt < 2; mt++)
                    MMA_BF16(acc[mt][nt], ah[mt], bb[nt]);
        }
    }

    const int grow0 = m0 + wm * 32 + (lid >> 2);
    const int gcol0 = n0 + wn * 64 + (lid & 3) * 2;
#pragma unroll
    for (int mt = 0; mt < 2; mt++) {
#pragma unroll
        for (int nt = 0; nt < 8; nt++) {
            int r0 = grow0 + mt * 16;
            int c0 = gcol0 + nt * 8;
            float2 v0 = make_float2(acc[mt][nt][0], acc[mt][nt][1]);
            float2 v1 = make_float2(acc[mt][nt][2], acc[mt][nt][3]);
            if (OUT == 0) {
                *(float2*)(C + (size_t)r0 * N + c0) = v0;
                *(float2*)(C + (size_t)(r0 + 8) * N + c0) = v1;
            } else {
                uint32_t h0 = pack_bf2(v0.x, v0.y);
                uint32_t h1 = pack_bf2(v1.x, v1.y);
                *(uint32_t*)(Chi + (size_t)r0 * N + c0) = h0;
                *(uint32_t*)(Chi + (size_t)(r0 + 8) * N + c0) = h1;
                __nv_bfloat162 hh0 = *(__nv_bfloat162*)&h0;
                __nv_bfloat162 hh1 = *(__nv_bfloat162*)&h1;
                *(uint32_t*)(Clo + (size_t)r0 * N + c0) =
                    pack_bf2(v0.x - __bfloat162float(hh0.x),
                             v0.y - __bfloat162float(hh0.y));
                *(uint32_t*)(Clo + (size_t)(r0 + 8) * N + c0) =
                    pack_bf2(v1.x - __bfloat162float(hh1.x),
                             v1.y - __bfloat162float(hh1.y));
            }
        }
    }
}

// split-K x2 GEMM: grid = 2 * (M/128)*(N/128); halves write P0 / P1.
__global__ __launch_bounds__(256, 2) void bgemm_splitk(
    const __nv_bfloat16* __restrict__ Ahi, const __nv_bfloat16* __restrict__ Alo,
    const __nv_bfloat16* __restrict__ Bhi, const __nv_bfloat16* __restrict__ Blo,
    float* __restrict__ P0, float* __restrict__ P1,
    int N, int K, int Khalf)
{
    const int per = gridDim.x >> 1;
    int id = blockIdx.x;
    const int half = (id >= per) ? 1 : 0;
    if (half) id -= per;
    const int ntn = N >> 7;
    const int m0 = (id / ntn) * 128, n0 = (id % ntn) * 128;
    const int ko = half * Khalf;
    bgemm_body<0>(Ahi + ko, Alo + ko, Bhi + ko, Blo + ko,
                  half ? P1 : P0, nullptr, nullptr, N, K, Khalf, m0, n0);
}

// q (full-K, direct split out) + k/v (split-K x2 into partials), one launch.
// ids: [0,128) q; [128,224) k half0; [224,320) k half1; [320,416) v h0; [416,512) v h1
__global__ __launch_bounds__(256, 2) void bgemm_qkv(
    const __nv_bfloat16* __restrict__ ct_hi, const __nv_bfloat16* __restrict__ ct_lo,
    const __nv_bfloat16* __restrict__ res_hi, const __nv_bfloat16* __restrict__ res_lo,
    const __nv_bfloat16* __restrict__ qw_hi, const __nv_bfloat16* __restrict__ qw_lo,
    const __nv_bfloat16* __restrict__ kw_hi, const __nv_bfloat16* __restrict__ kw_lo,
    const __nv_bfloat16* __restrict__ vw_hi, const __nv_bfloat16* __restrict__ vw_lo,
    __nv_bfloat16* __restrict__ q_hi, __nv_bfloat16* __restrict__ q_lo,
    float* __restrict__ pk0, float* __restrict__ pk1,
    float* __restrict__ pv0, float* __restrict__ pv1)
{
    int id = blockIdx.x;
    if (id < 128) {
        bgemm_body<1>(ct_hi, ct_lo, qw_hi, qw_lo, nullptr, q_hi, q_lo,
                      2048, 2048, 2048, (id >> 4) * 128, (id & 15) * 128);
    } else {
        int id2 = id - 128;
        const int part = id2 / 96;       // 0:k-h0 1:k-h1 2:v-h0 3:v-h1
        const int t = id2 % 96;
        const int half = part & 1, isv = part >> 1;
        const int ko = half * 1024;
        const __nv_bfloat16* bh = (isv ? vw_hi : kw_hi) + ko;
        const __nv_bfloat16* bl = (isv ? vw_lo : kw_lo) + ko;
        float* P = isv ? (half ? pv1 : pv0) : (half ? pk1 : pk0);
        bgemm_body<0>(res_hi + ko, res_lo + ko, bh, bl, P, nullptr, nullptr,
                      512, 2048, 1024, (t >> 2) * 128, (t & 3) * 128);
    }
}

// gate + up in one launch (704 tiles, fp32 out).
__global__ __launch_bounds__(256, 2) void bgemm_gateup(
    const __nv_bfloat16* __restrict__ ct_hi, const __nv_bfloat16* __restrict__ ct_lo,
    const __nv_bfloat16* __restrict__ gw_hi, const __nv_bfloat16* __restrict__ gw_lo,
    const __nv_bfloat16* __restrict__ uw_hi, const __nv_bfloat16* __restrict__ uw_lo,
    float* __restrict__ gate, float* __restrict__ up)
{
    int id = blockIdx.x;
    if (id < 352) {
        bgemm_body<0>(ct_hi, ct_lo, gw_hi, gw_lo, gate, nullptr, nullptr,
                      5632, 2048, 2048, (id / 44) * 128, (id % 44) * 128);
    } else {
        id -= 352;
        bgemm_body<0>(ct_hi, ct_lo, uw_hi, uw_lo, up, nullptr, nullptr,
                      5632, 2048, 2048, (id / 44) * 128, (id % 44) * 128);
    }
}

// ==================== split-K reduce: C = P0 + P1 (+bias/+ct), opt hi/lo ====
template <int BIAS, int CT, int OF32, int OSPLIT>
__global__ void reduce2(const float* __restrict__ P0, const float* __restrict__ P1,
                        const float* __restrict__ aux, float* __restrict__ C,
                        __nv_bfloat16* __restrict__ hi, __nv_bfloat16* __restrict__ lo,
                        int n4, int rowdiv)
{
    int i = blockIdx.x * 1024 + threadIdx.x;
#pragma unroll
    for (int u = 0; u < 4; u++, i += 256) {
        if (i < n4) {
            float4 a = ((const float4*)P0)[i];
            float4 b = ((const float4*)P1)[i];
            float4 v = make_float4(a.x + b.x, a.y + b.y, a.z + b.z, a.w + b.w);
            if (BIAS) {
                float bb = aux[i / rowdiv];
                v.x += bb; v.y += bb; v.z += bb; v.w += bb;
            }
            if (CT) {
                float4 c = ((const float4*)aux)[i];
                v.x += c.x; v.y += c.y; v.z += c.z; v.w += c.w;
            }
            if (OF32) ((float4*)C)[i] = v;
            if (OSPLIT) {
                uint32_t h0 = pack_bf2(v.x, v.y), h1 = pack_bf2(v.z, v.w);
                ((uint32_t*)hi)[i * 2]     = h0;
                ((uint32_t*)hi)[i * 2 + 1] = h1;
                __nv_bfloat162 a0 = *(__nv_bfloat162*)&h0;
                __nv_bfloat162 a1 = *(__nv_bfloat162*)&h1;
                ((uint32_t*)lo)[i * 2] =
                    pack_bf2(v.x - __bfloat162float(a0.x), v.y - __bfloat162float(a0.y));
                ((uint32_t*)lo)[i * 2 + 1] =
                    pack_bf2(v.z - __bfloat162float(a1.x), v.w - __bfloat162float(a1.y));
            }
        }
    }
}

// ==================== HMMA split-bf16 flash attention (2-stage, 4/SM) ======
__global__ __launch_bounds__(128, 4) void attn_mma(
    const __nv_bfloat16* __restrict__ Qhi, const __nv_bfloat16* __restrict__ Qlo,
    const __nv_bfloat16* __restrict__ Khi, const __nv_bfloat16* __restrict__ Klo,
    const __nv_bfloat16* __restrict__ Vhi, const __nv_bfloat16* __restrict__ Vlo,
    __nv_bfloat16* __restrict__ Ohi, __nv_bfloat16* __restrict__ Olo)
{
    extern __shared__ char sm[];
    const int tid = threadIdx.x;
    const int wid = tid >> 5, lid = tid & 31;
    const int q0 = blockIdx.x * 64;
    const int head = blockIdx.y;
    const int kvoff = (head >> 2) * 64;
    const uint32_t sb = smem_u32(sm);
    const uint32_t sQh = sb, sQl = sb + 8192;
    const uint32_t sKV = sb + 16384;   // 2 stages x 16KB

#pragma unroll
    for (int i = 0; i < 4; i++) {
        int f = tid + i * 128;
        int r = f >> 3, c = f & 7;
        uint32_t off = (uint32_t)(r * 128) + (uint32_t)((c * 16) ^ ((r & 7) << 4));
        size_t g = (size_t)(q0 + r) * 2048 + head * 64 + c * 8;
        CP_ASYNC16(sQh + off, Qhi + g);
        CP_ASYNC16(sQl + off, Qlo + g);
    }
    CP_COMMIT();

#define ISSUE_KV(t0, st)                                                       \
    {                                                                          \
        uint32_t s_ = sKV + (uint32_t)(st) * 16384;                            \
        _Pragma("unroll")                                                      \
        for (int i_ = 0; i_ < 2; i_++) {                                       \
            int f_ = tid + i_ * 128;                                           \
            int r_ = f_ >> 3, c_ = f_ & 7;                                     \
            uint32_t o_ = (uint32_t)(r_ * 128) +                               \
                          (uint32_t)((c_ * 16) ^ ((r_ & 7) << 4));             \
            size_t g_ = (size_t)((t0) + r_) * 512 + kvoff + c_ * 8;            \
            CP_ASYNC16(s_ + o_,         Khi + g_);                             \
            CP_ASYNC16(s_ + 4096 + o_,  Klo + g_);                             \
            CP_ASYNC16(s_ + 8192 + o_,  Vhi + g_);                             \
            CP_ASYNC16(s_ + 12288 + o_, Vlo + g_);                             \
        }                                                                      \
    }

    ISSUE_KV(0, 0);  CP_COMMIT();
    ISSUE_KV(32, 1); CP_COMMIT();

    CP_WAIT1();            // Q + KV0 ready, KV1 pending
    __syncthreads();

    uint32_t qh[4][4], ql[4][4];
    {
        const int ar = (lid & 7) + ((lid >> 3) & 1) * 8;
        const int row = wid * 16 + ar;
        const uint32_t khalf = (uint32_t)((lid >> 4) & 1) * 16;
#pragma unroll
        for (int ks = 0; ks < 4; ks++) {
            uint32_t off = (uint32_t)(row * 128) +
                           ((khalf + (uint32_t)ks * 32) ^ ((uint32_t)(ar & 7) << 4));
            LDSM_X4(qh[ks][0], qh[ks][1], qh[ks][2], qh[ks][3], sQh + off);
            LDSM_X4(ql[ks][0], ql[ks][1], ql[ks][2], ql[ks][3], sQl + off);
        }
    }

    float acc_o[8][4];
#pragma unroll
    for (int d = 0; d < 8; d++)
#pragma unroll
        for (int e = 0; e < 4; e++) acc_o[d][e] = 0.f;
    float mr0 = -1e30f, mr1 = -1e30f, lr0 = 0.f, lr1 = 0.f;

    const int brS = (lid & 7) + ((lid >> 4) & 1) * 8;
    const uint32_t bkS = (uint32_t)((lid >> 3) & 1) * 16;
    const int trV = (lid & 7) + ((lid >> 3) & 1) * 8;
    const uint32_t dkV = (uint32_t)((lid >> 4) & 1) * 16;

    for (int t = 0; t < 96; t++) {
        const uint32_t st = sKV + (uint32_t)(t & 1) * 16384;

        float s[4][4];
#pragma unroll
        for (int nt = 0; nt < 4; nt++)
#pragma unroll
            for (int e = 0; e < 4; e++) s[nt][e] = 0.f;
#pragma unroll
        for (int ks = 0; ks < 4; ks++) {
            uint32_t bh[4][2], bl[4][2];
#pragma unroll
            for (int p = 0; p < 2; p++) {
                int rr = p * 16 + brS;
                uint32_t off = (uint32_t)(rr * 128) +
                               ((bkS + (uint32_t)ks * 32) ^ ((uint32_t)(rr & 7) << 4));
                LDSM_X4(bh[2*p][0], bh[2*p][1], bh[2*p+1][0], bh[2*p+1][1], st + off);
                LDSM_X4(bl[2*p][0], bl[2*p][1], bl[2*p+1][0], bl[2*p+1][1], st + 4096 + off);
            }
#pragma unroll
            for (int nt = 0; nt < 4; nt++) {
                MMA_BF16(s[nt], qh[ks], bh[nt]);
                MMA_BF16(s[nt], qh[ks], bl[nt]);
                MMA_BF16(s[nt], ql[ks], bh[nt]);
            }
        }

        float mn0 = mr0, mn1 = mr1;
#pragma unroll
        for (int nt = 0; nt < 4; nt++) {
            s[nt][0] *= 0.125f; s[nt][1] *= 0.125f;
            s[nt][2] *= 0.125f; s[nt][3] *= 0.125f;
            mn0 = fmaxf(mn0, fmaxf(s[nt][0], s[nt][1]));
            mn1 = fmaxf(mn1, fmaxf(s[nt][2], s[nt][3]));
        }
        mn0 = fmaxf(mn0, __shfl_xor_sync(0xffffffffu, mn0, 1));
        mn0 = fmaxf(mn0, __shfl_xor_sync(0xffffffffu, mn0, 2));
        mn1 = fmaxf(mn1, __shfl_xor_sync(0xffffffffu, mn1, 1));
        mn1 = fmaxf(mn1, __shfl_xor_sync(0xffffffffu, mn1, 2));
        float f0 = __expf(mr0 - mn0), f1 = __expf(mr1 - mn1);
        mr0 = mn0; mr1 = mn1;
        float ps0 = 0.f, ps1 = 0.f;
#pragma unroll
        for (int nt = 0; nt < 4; nt++) {
            s[nt][0] = __expf(s[nt][0] - mn0);
            s[nt][1] = __expf(s[nt][1] - mn0);
            s[nt][2] = __expf(s[nt][2] - mn1);
            s[nt][3] = __expf(s[nt][3] - mn1);
            ps0 += s[nt][0] + s[nt][1];
            ps1 += s[nt][2] + s[nt][3];
        }
        lr0 = lr0 * f0 + ps0;
        lr1 = lr1 * f1 + ps1;
#pragma unroll
        for (int d = 0; d < 8; d++) {
            acc_o[d][0] *= f0; acc_o[d][1] *= f0;
            acc_o[d][2] *= f1; acc_o[d][3] *= f1;
        }

#pragma unroll
        for (int j = 0; j < 2; j++) {
            uint32_t ah[4], al[4];
            {
                float p00 = s[2*j][0],   p01 = s[2*j][1];
                float p02 = s[2*j][2],   p03 = s[2*j][3];
                float p10 = s[2*j+1][0], p11 = s[2*j+1][1];
                float p12 = s[2*j+1][2], p13 = s[2*j+1][3];
                ah[0] = pack_bf2(p00, p01); ah[1] = pack_bf2(p02, p03);
                ah[2] = pack_bf2(p10, p11); ah[3] = pack_bf2(p12, p13);
#pragma unroll
                for (int e = 0; e < 4; e++) {
                    __nv_bfloat162 hh = *(__nv_bfloat162*)&ah[e];
                    float x0, x1;
                    if (e == 0) { x0 = p00; x1 = p01; }
                    else if (e == 1) { x0 = p02; x1 = p03; }
                    else if (e == 2) { x0 = p10; x1 = p11; }
                    else { x0 = p12; x1 = p13; }
                    al[e] = pack_bf2(x0 - __bfloat162float(hh.x),
                                     x1 - __bfloat162float(hh.y));
                }
            }
            const int rr = j * 16 + trV;
#pragma unroll
            for (int dp = 0; dp < 4; dp++) {
                uint32_t off = (uint32_t)(rr * 128) +
                               ((dkV + (uint32_t)dp * 32) ^ ((uint32_t)(rr & 7) << 4));
                uint32_t vh[4], vl[4];
                LDSM_X4_T(vh[0], vh[1], vh[2], vh[3], st + 8192 + off);
                LDSM_X4_T(vl[0], vl[1], vl[2], vl[3], st + 12288 + off);
                uint32_t b0h[2] = {vh[0], vh[1]}, b1h[2] = {vh[2], vh[3]};
                uint32_t b0l[2] = {vl[0], vl[1]}, b1l[2] = {vl[2], vl[3]};
                MMA_BF16(acc_o[2*dp],   ah, b0h);
                MMA_BF16(acc_o[2*dp],   ah, b0l);
                MMA_BF16(acc_o[2*dp],   al, b0h);
                MMA_BF16(acc_o[2*dp+1], ah, b1h);
                MMA_BF16(acc_o[2*dp+1], ah, b1l);
                MMA_BF16(acc_o[2*dp+1], al, b1h);
            }
        }

        // pipeline: refill just-consumed stage with tile t+2, wait for t+1
        __syncthreads();
        if (t + 2 < 96) ISSUE_KV((t + 2) * 32, t & 1);
        CP_COMMIT();
        if (t + 1 < 96) { CP_WAIT1(); __syncthreads(); }
    }

    lr0 += __shfl_xor_sync(0xffffffffu, lr0, 1);
    lr0 += __shfl_xor_sync(0xffffffffu, lr0, 2);
    lr1 += __shfl_xor_sync(0xffffffffu, lr1, 1);
    lr1 += __shfl_xor_sync(0xffffffffu, lr1, 2);
    float il0 = 1.f / lr0, il1 = 1.f / lr1;
    const int row0 = q0 + wid * 16 + (lid >> 2);
    const int col0 = head * 64 + (lid & 3) * 2;
#pragma unroll
    for (int d = 0; d < 8; d++) {
        int col = col0 + d * 8;
        float o0 = acc_o[d][0] * il0, o1 = acc_o[d][1] * il0;
        float o2 = acc_o[d][2] * il1, o3 = acc_o[d][3] * il1;
        uint32_t h0 = pack_bf2(o0, o1), h1 = pack_bf2(o2, o3);
        *(uint32_t*)(Ohi + (size_t)row0 * 2048 + col) = h0;
        *(uint32_t*)(Ohi + (size_t)(row0 + 8) * 2048 + col) = h1;
        __nv_bfloat162 hh0 = *(__nv_bfloat162*)&h0;
        __nv_bfloat162 hh1 = *(__nv_bfloat162*)&h1;
        *(uint32_t*)(Olo + (size_t)row0 * 2048 + col) =
            pack_bf2(o0 - __bfloat162float(hh0.x), o1 - __bfloat162float(hh0.y));
        *(uint32_t*)(Olo + (size_t)(row0 + 8) * 2048 + col) =
            pack_bf2(o2 - __bfloat162float(hh1.x), o3 - __bfloat162float(hh1.y));
    }
}

// -------------------- conversion / elementwise kernels --------------------
__global__ void split_kernel(const float* __restrict__ x,
                             __nv_bfloat16* __restrict__ hi,
                             __nv_bfloat16* __restrict__ lo, int n4)
{
    int i = blockIdx.x * 1024 + threadIdx.x;
#pragma unroll
    for (int u = 0; u < 4; u++, i += 256) {
        if (i < n4) {
            float4 v = ((const float4*)x)[i];
            uint32_t h0 = pack_bf2(v.x, v.y), h1 = pack_bf2(v.z, v.w);
            ((uint32_t*)hi)[i * 2]     = h0;
            ((uint32_t*)hi)[i * 2 + 1] = h1;
            __nv_bfloat162 a0 = *(__nv_bfloat162*)&h0;
            __nv_bfloat162 a1 = *(__nv_bfloat162*)&h1;
            ((uint32_t*)lo)[i * 2] =
                pack_bf2(v.x - __bfloat162float(a0.x), v.y - __bfloat162float(a0.y));
            ((uint32_t*)lo)[i * 2 + 1] =
                pack_bf2(v.z - __bfloat162float(a1.x), v.w - __bfloat162float(a1.y));
        }
    }
}

__global__ void transpose_split(const float* __restrict__ x,
                                __nv_bfloat16* __restrict__ hiT,
                                __nv_bfloat16* __restrict__ loT, int R, int C)
{
    __shared__ float t[32][33];
    int c0 = blockIdx.x * 32, r0 = blockIdx.y * 32;
    for (int i = threadIdx.y; i < 32; i += 8)
        t[i][threadIdx.x] = x[(size_t)(r0 + i) * C + c0 + threadIdx.x];
    __syncthreads();
    for (int i = threadIdx.y; i < 32; i += 8) {
        float v = t[threadIdx.x][i];
        __nv_bfloat16 h = __float2bfloat16(v);
        size_t o = (size_t)(c0 + i) * R + r0 + threadIdx.x;
        hiT[o] = h;
        loT[o] = __float2bfloat16(v - __bfloat162float(h));
    }
}

__global__ void rmsnorm_kernel(const float* __restrict__ x,
                               const float* __restrict__ w,
                               float* __restrict__ y,
                               __nv_bfloat16* __restrict__ yhi,
                               __nv_bfloat16* __restrict__ ylo)
{
    const int row = blockIdx.x;
    const float* xr = x + (size_t)row * 2048;
    float ss = 0.f;
    for (int i = threadIdx.x; i < 2048; i += 256) { float v = xr[i]; ss += v * v; }
    __shared__ float red[256];
    red[threadIdx.x] = ss;
    __syncthreads();
    for (int s = 128; s > 0; s >>= 1) {
        if (threadIdx.x < s) red[threadIdx.x] += red[threadIdx.x + s];
        __syncthreads();
    }
    __shared__ float inv;
    if (threadIdx.x == 0) inv = rsqrtf(red[0] * (1.f / 2048.f) + 1e-6f);
    __syncthreads();
    float iv = inv;
    for (int i = threadIdx.x; i < 2048; i += 256) {
        float v = xr[i] * iv * w[i];
        size_t o = (size_t)row * 2048 + i;
        y[o] = v;
        __nv_bfloat16 h = __float2bfloat16(v);
        yhi[o] = h;
        ylo[o] = __float2bfloat16(v - __bfloat162float(h));
    }
}

__global__ void swiglu_split(const float* __restrict__ g, const float* __restrict__ u,
                             __nv_bfloat16* __restrict__ hi, __nv_bfloat16* __restrict__ lo,
                             int n)
{
    int i = blockIdx.x * blockDim.x + threadIdx.x;
    if (i < n) {
        float x = g[i];
        float v = (x / (1.f + __expf(-x))) * u[i];
        __nv_bfloat16 h = __float2bfloat16(v);
        hi[i] = h;
        lo[i] = __float2bfloat16(v - __bfloat162float(h));
    }
}

// -------------------- orchestration --------------------
static const int SMEM_GEMM = 3 * 32768;          // 96KB
static const int SMEM_ATTN = 16384 + 2 * 16384;  // 48KB -> 4 CTAs/SM

extern "C" void kernel_launch(void* const* d_in, const int* in_sizes, int n_in,
                              void* d_out, int out_size)
{
    (void)in_sizes; (void)n_in; (void)out_size;
    const float* hidden      = (const float*)d_in[0];
    const float* comp_w      = (const float*)d_in[1];
    const float* comp_b      = (const float*)d_in[2];
    const float* q_w         = (const float*)d_in[3];
    const float* k_w         = (const float*)d_in[4];
    const float* v_w         = (const float*)d_in[5];
    const float* o_w         = (const float*)d_in[6];
    const float* attn_norm_w = (const float*)d_in[7];
    const float* mlp_norm_w  = (const float*)d_in[8];
    const float* gate_w      = (const float*)d_in[9];
    const float* up_w        = (const float*)d_in[10];
    const float* down_w      = (const float*)d_in[11];
    float* out = (float*)d_out;

    cudaFuncSetAttribute(bgemm_splitk, cudaFuncAttributeMaxDynamicSharedMemorySize, SMEM_GEMM);
    cudaFuncSetAttribute(bgemm_qkv,    cudaFuncAttributeMaxDynamicSharedMemorySize, SMEM_GEMM);
    cudaFuncSetAttribute(bgemm_gateup, cudaFuncAttributeMaxDynamicSharedMemorySize, SMEM_GEMM);
    cudaFuncSetAttribute(attn_mma,     cudaFuncAttributeMaxDynamicSharedMemorySize, SMEM_ATTN);

    float *compressed, *ct, *gate, *up, *p0, *p1, *pk0, *pk1, *pv0, *pv1;
    cudaGetSymbolAddress((void**)&compressed, g_compressed);
    cudaGetSymbolAddress((void**)&ct,   g_ct);
    cudaGetSymbolAddress((void**)&gate, g_gate);
    cudaGetSymbolAddress((void**)&up,   g_up);
    cudaGetSymbolAddress((void**)&p0,   g_p0);
    cudaGetSymbolAddress((void**)&p1,   g_p1);
    cudaGetSymbolAddress((void**)&pk0,  g_pk0);
    cudaGetSymbolAddress((void**)&pk1,  g_pk1);
    cudaGetSymbolAddress((void**)&pv0,  g_pv0);
    cudaGetSymbolAddress((void**)&pv1,  g_pv1);

    __nv_bfloat16 *res_hi, *res_lo, *ct_hi, *ct_lo, *ao_hi, *ao_lo, *ga_hi, *ga_lo,
                  *hT_hi, *hT_lo, *q_hi, *q_lo, *k_hi, *k_lo, *v_hi, *v_lo,
                  *cw_hi, *cw_lo, *qw_hi, *qw_lo, *kw_hi, *kw_lo,
                  *vw_hi, *vw_lo, *ow_hi, *ow_lo, *gw_hi, *gw_lo, *uw_hi, *uw_lo,
                  *dw_hi, *dw_lo;
    cudaGetSymbolAddress((void**)&res_hi, g_res_hi); cudaGetSymbolAddress((void**)&res_lo, g_res_lo);
    cudaGetSymbolAddress((void**)&ct_hi,  g_ct_hi);  cudaGetSymbolAddress((void**)&ct_lo,  g_ct_lo);
    cudaGetSymbolAddress((void**)&ao_hi,  g_ao_hi);  cudaGetSymbolAddress((void**)&ao_lo,  g_ao_lo);
    cudaGetSymbolAddress((void**)&ga_hi,  g_ga_hi);  cudaGetSymbolAddress((void**)&ga_lo,  g_ga_lo);
    cudaGetSymbolAddress((void**)&hT_hi,  g_hT_hi);  cudaGetSymbolAddress((void**)&hT_lo,  g_hT_lo);
    cudaGetSymbolAddress((void**)&q_hi,   g_q_hi);   cudaGetSymbolAddress((void**)&q_lo,   g_q_lo);
    cudaGetSymbolAddress((void**)&k_hi,   g_k_hi);   cudaGetSymbolAddress((void**)&k_lo,   g_k_lo);
    cudaGetSymbolAddress((void**)&v_hi,   g_v_hi);   cudaGetSymbolAddress((void**)&v_lo,   g_v_lo);
    cudaGetSymbolAddress((void**)&cw_hi,  g_cw_hi);  cudaGetSymbolAddress((void**)&cw_lo,  g_cw_lo);
    cudaGetSymbolAddress((void**)&qw_hi,  g_qw_hi);  cudaGetSymbolAddress((void**)&qw_lo,  g_qw_lo);
    cudaGetSymbolAddress((void**)&kw_hi,  g_kw_hi);  cudaGetSymbolAddress((void**)&kw_lo,  g_kw_lo);
    cudaGetSymbolAddress((void**)&vw_hi,  g_vw_hi);  cudaGetSymbolAddress((void**)&vw_lo,  g_vw_lo);
    cudaGetSymbolAddress((void**)&ow_hi,  g_ow_hi);  cudaGetSymbolAddress((void**)&ow_lo,  g_ow_lo);
    cudaGetSymbolAddress((void**)&gw_hi,  g_gw_hi);  cudaGetSymbolAddress((void**)&gw_lo,  g_gw_lo);
    cudaGetSymbolAddress((void**)&uw_hi,  g_uw_hi);  cudaGetSymbolAddress((void**)&uw_lo,  g_uw_lo);
    cudaGetSymbolAddress((void**)&dw_hi,  g_dw_hi);  cudaGetSymbolAddress((void**)&dw_lo,  g_dw_lo);

    auto split = [&](const float* src, __nv_bfloat16* hi, __nv_bfloat16* lo, int n) {
        int n4 = n / 4;
        split_kernel<<<(n4 + 1023) / 1024, 256>>>(src, hi, lo, n4);
    };

    split(comp_w, cw_hi, cw_lo, 1024 * 2048);
    split(q_w,    qw_hi, qw_lo, 2048 * 2048);
    split(k_w,    kw_hi, kw_lo, 512 * 2048);
    split(v_w,    vw_hi, vw_lo, 512 * 2048);
    split(o_w,    ow_hi, ow_lo, 2048 * 2048);
    split(gate_w, gw_hi, gw_lo, 5632 * 2048);
    split(up_w,   uw_hi, uw_lo, 5632 * 2048);
    split(down_w, dw_hi, dw_lo, 2048 * 5632);
    transpose_split<<<dim3(64, 64), dim3(32, 8)>>>(hidden, hT_hi, hT_lo, 2048, 2048);
    split(hidden, res_hi, res_lo, 2048 * 2048);

    const int N4 = 1024 * 2048 / 4;        // 524288
    const int KV4 = 3072 * 512 / 4;        // 393216

    // compressed = comp_w @ hidden + comp_b (split-K2), + residual split rows
    bgemm_splitk<<<256, 256, SMEM_GEMM>>>(cw_hi, cw_lo, hT_hi, hT_lo,
                                          p0, p1, 2048, 2048, 1024);
    reduce2<1,0,1,1><<<N4 / 1024, 256>>>(p0, p1, comp_b, compressed,
        res_hi + 2048 * 2048, res_lo + 2048 * 2048, N4, 512);

    for (int layer = 0; layer < 2; layer++) {
        rmsnorm_kernel<<<1024, 256>>>(compressed, attn_norm_w, ct, ct_hi, ct_lo);

        bgemm_qkv<<<512, 256, SMEM_GEMM>>>(ct_hi, ct_lo, res_hi, res_lo,
            qw_hi, qw_lo, kw_hi, kw_lo, vw_hi, vw_lo,
            q_hi, q_lo, pk0, pk1, pv0, pv1);
        reduce2<0,0,0,1><<<KV4 / 1024, 256>>>(pk0, pk1, nullptr, nullptr,
                                              k_hi, k_lo, KV4, 0);
        reduce2<0,0,0,1><<<KV4 / 1024, 256>>>(pv0, pv1, nullptr, nullptr,
                                              v_hi, v_lo, KV4, 0);

        attn_mma<<<dim3(16, 32), 128, SMEM_ATTN>>>(q_hi, q_lo, k_hi, k_lo,
                                                   v_hi, v_lo, ao_hi, ao_lo);

        // compressed = attno @ o_w^T + ct (split-K2)
        bgemm_splitk<<<256, 256, SMEM_GEMM>>>(ao_hi, ao_lo, ow_hi, ow_lo,
                                              p0, p1, 2048, 2048, 1024);
        reduce2<0,1,1,0><<<N4 / 1024, 256>>>(p0, p1, ct, compressed,
                                             nullptr, nullptr, N4, 0);

        rmsnorm_kernel<<<1024, 256>>>(compressed, mlp_norm_w, ct, ct_hi, ct_lo);

        bgemm_gateup<<<704, 256, SMEM_GEMM>>>(ct_hi, ct_lo, gw_hi, gw_lo,
                                              uw_hi, uw_lo, gate, up);
        swiglu_split<<<(1024 * 5632 + 255) / 256, 256>>>(gate, up, ga_hi, ga_lo,
                                                         1024 * 5632);

        // down-proj (split-K2, K=5632) + ct2 residual
        bgemm_splitk<<<256, 256, SMEM_GEMM>>>(ga_hi, ga_lo, dw_hi, dw_lo,
                                              p0, p1, 2048, 5632, 2816);
        if (layer == 0) {
            reduce2<0,1,1,1><<<N4 / 1024, 256>>>(p0, p1, ct, compressed,
                res_hi + 2048 * 2048, res_lo + 2048 * 2048, N4, 0);
        } else {
            reduce2<0,1,1,0><<<N4 / 1024, 256>>>(p0, p1, ct, out,
                                                 nullptr, nullptr, N4, 0);
        }
    }
}